// round 1
// baseline (speedup 1.0000x reference)
#include <cuda_runtime.h>
#include <cuda_bf16.h>
#include <math.h>

// ---------------------------------------------------------------------------
// BasicTransformerBlock (stable-diffusion style) on GB300, fp32 baseline.
// x:[8,1024,512], enc:[8,77,768]. Heads=8, dim_head=64.
// Pipeline: LN -> QKV gemm -> flash-attn -> out-proj(+res) -> LN -> cross ->
//           out-proj(+res) -> LN -> GEGLU gemm -> act -> gemm(+res) -> out
// ---------------------------------------------------------------------------

#define DIM 512
#define ROWS 8192          // 8*1024
#define CROSS_ROWS 616     // 8*77
#define CROSS_DIM 768
#define FF_INNER 2048
#define FF2 4096

// scratch (device globals: allocation-free per harness rules)
__device__ float g_h[ROWS * DIM];
__device__ float g_q[ROWS * DIM];
__device__ float g_k[ROWS * DIM];
__device__ float g_v[ROWS * DIM];
__device__ float g_a[ROWS * DIM];
__device__ float g_x1[ROWS * DIM];
__device__ float g_x2[ROWS * DIM];
__device__ float g_proj[ROWS * FF2];
__device__ float g_act[ROWS * FF_INNER];

// ---------------------------------------------------------------------------
// LayerNorm: one warp per row of 512
// ---------------------------------------------------------------------------
__global__ __launch_bounds__(256) void ln_kernel(
    const float* __restrict__ x, const float* __restrict__ g,
    const float* __restrict__ b, float* __restrict__ out, int rows)
{
    int row = blockIdx.x * 8 + (threadIdx.x >> 5);
    int lane = threadIdx.x & 31;
    if (row >= rows) return;
    const float4* xr = (const float4*)(x + (size_t)row * DIM);
    float4 v[4];
    float sum = 0.f, sq = 0.f;
#pragma unroll
    for (int i = 0; i < 4; i++) {
        v[i] = xr[lane + i * 32];
        sum += v[i].x + v[i].y + v[i].z + v[i].w;
        sq  += v[i].x*v[i].x + v[i].y*v[i].y + v[i].z*v[i].z + v[i].w*v[i].w;
    }
#pragma unroll
    for (int off = 16; off; off >>= 1) {
        sum += __shfl_xor_sync(0xffffffffu, sum, off);
        sq  += __shfl_xor_sync(0xffffffffu, sq,  off);
    }
    float mean = sum * (1.f / DIM);
    float var  = sq * (1.f / DIM) - mean * mean;
    float rstd = rsqrtf(var + 1e-5f);
    float4* outr = (float4*)(out + (size_t)row * DIM);
#pragma unroll
    for (int i = 0; i < 4; i++) {
        int c = (lane + i * 32) * 4;
        float4 gg = *(const float4*)&g[c];
        float4 bb = *(const float4*)&b[c];
        float4 o;
        o.x = (v[i].x - mean) * rstd * gg.x + bb.x;
        o.y = (v[i].y - mean) * rstd * gg.y + bb.y;
        o.z = (v[i].z - mean) * rstd * gg.z + bb.z;
        o.w = (v[i].w - mean) * rstd * gg.w + bb.w;
        outr[lane + i * 32] = o;
    }
}

// ---------------------------------------------------------------------------
// SGEMM: C[M,N] = A[M,K] @ B[K,N] (+bias[N]) (+res[M,N])
// 128x128x16 tile, 256 threads, 8x8 per thread (two 4-wide fragments).
// Requires N % 128 == 0, K % 16 == 0. M guarded.
// ---------------------------------------------------------------------------
template <bool BIAS, bool RES>
__global__ __launch_bounds__(256) void sgemm(
    const float* __restrict__ A, const float* __restrict__ B,
    const float* __restrict__ bias, const float* __restrict__ res,
    float* __restrict__ C, int M, int N, int K)
{
    __shared__ float As[16][128];
    __shared__ float Bs[16][128];
    int tid = threadIdx.x;
    int tx = tid & 15, ty = tid >> 4;
    int m0 = blockIdx.y * 128, n0 = blockIdx.x * 128;
    float acc[8][8] = {};
    int arow = tid >> 2, acol = (tid & 3) * 4;
    int brow = tid >> 5, bcol = (tid & 31) * 4;

    for (int k0 = 0; k0 < K; k0 += 16) {
#pragma unroll
        for (int i = 0; i < 2; i++) {
            int m = m0 + arow + i * 64;
            float4 a = (m < M) ? *(const float4*)&A[(size_t)m * K + k0 + acol]
                               : make_float4(0.f, 0.f, 0.f, 0.f);
            As[acol + 0][arow + i * 64] = a.x;
            As[acol + 1][arow + i * 64] = a.y;
            As[acol + 2][arow + i * 64] = a.z;
            As[acol + 3][arow + i * 64] = a.w;
        }
#pragma unroll
        for (int i = 0; i < 2; i++) {
            float4 bb = *(const float4*)&B[(size_t)(k0 + brow + i * 8) * N + n0 + bcol];
            *(float4*)&Bs[brow + i * 8][bcol] = bb;
        }
        __syncthreads();
#pragma unroll
        for (int kk = 0; kk < 16; kk++) {
            float4 a0 = *(const float4*)&As[kk][ty * 4];
            float4 a1 = *(const float4*)&As[kk][64 + ty * 4];
            float4 b0 = *(const float4*)&Bs[kk][tx * 4];
            float4 b1 = *(const float4*)&Bs[kk][64 + tx * 4];
            float av[8] = {a0.x, a0.y, a0.z, a0.w, a1.x, a1.y, a1.z, a1.w};
            float bv[8] = {b0.x, b0.y, b0.z, b0.w, b1.x, b1.y, b1.z, b1.w};
#pragma unroll
            for (int i = 0; i < 8; i++)
#pragma unroll
                for (int j = 0; j < 8; j++)
                    acc[i][j] = fmaf(av[i], bv[j], acc[i][j]);
        }
        __syncthreads();
    }
#pragma unroll
    for (int i = 0; i < 8; i++) {
        int m = m0 + ((i < 4) ? (ty * 4 + i) : (64 + ty * 4 + (i - 4)));
        if (m >= M) continue;
#pragma unroll
        for (int jj = 0; jj < 2; jj++) {
            int n = n0 + jj * 64 + tx * 4;
            float4 v;
            v.x = acc[i][jj * 4 + 0];
            v.y = acc[i][jj * 4 + 1];
            v.z = acc[i][jj * 4 + 2];
            v.w = acc[i][jj * 4 + 3];
            if (BIAS) {
                float4 bb = *(const float4*)&bias[n];
                v.x += bb.x; v.y += bb.y; v.z += bb.z; v.w += bb.w;
            }
            if (RES) {
                float4 rr = *(const float4*)&res[(size_t)m * N + n];
                v.x += rr.x; v.y += rr.y; v.z += rr.z; v.w += rr.w;
            }
            *(float4*)&C[(size_t)m * N + n] = v;
        }
    }
}

// ---------------------------------------------------------------------------
// Flash attention (fp32, online softmax).
// grid = (Sq/64, H=8, B=8), block = 256. Q pre-scaled by 1/8.
// Q/K/V/O laid out [B*rowsPerB, 512], head column offset h*64.
// ---------------------------------------------------------------------------
__global__ __launch_bounds__(256) void fattn(
    const float* __restrict__ Q, const float* __restrict__ K,
    const float* __restrict__ V, float* __restrict__ O,
    int kRowsPerB, int Sk)
{
    __shared__ float QsT[64][64];   // [d][row]
    __shared__ float KsT[64][64];   // [d][row]
    __shared__ float Vs[64][64];    // [row][d]
    __shared__ float Ps[64][64];    // [qrow][krow]

    int tid = threadIdx.x;
    int tx = tid & 15, ty = tid >> 4;
    int b = blockIdx.z, h = blockIdx.y;
    int q0 = blockIdx.x * 64;
    const int ld = DIM;
    int hoff = h * 64;
    size_t qbase = (size_t)b * 1024 * ld + hoff;
    size_t kbase = (size_t)b * kRowsPerB * ld + hoff;

    {
        int row = tid >> 4;
        int c4 = (tid & 15) * 4;
#pragma unroll
        for (int it = 0; it < 4; it++) {
            int r = row + it * 16;
            float4 qv = *(const float4*)&Q[qbase + (size_t)(q0 + r) * ld + c4];
            QsT[c4 + 0][r] = qv.x * 0.125f;
            QsT[c4 + 1][r] = qv.y * 0.125f;
            QsT[c4 + 2][r] = qv.z * 0.125f;
            QsT[c4 + 3][r] = qv.w * 0.125f;
        }
    }

    float m_i[4], l_i[4], o[4][4] = {};
#pragma unroll
    for (int i = 0; i < 4; i++) { m_i[i] = -1e30f; l_i[i] = 0.f; }

    int nkt = (Sk + 63) / 64;
    for (int kt = 0; kt < nkt; kt++) {
        __syncthreads();
        {
            int row = tid >> 4;
            int c4 = (tid & 15) * 4;
#pragma unroll
            for (int it = 0; it < 4; it++) {
                int r = row + it * 16;
                int gr = kt * 64 + r;
                float4 kv, vv;
                if (gr < Sk) {
                    kv = *(const float4*)&K[kbase + (size_t)gr * ld + c4];
                    vv = *(const float4*)&V[kbase + (size_t)gr * ld + c4];
                } else {
                    kv = make_float4(0.f, 0.f, 0.f, 0.f);
                    vv = kv;
                }
                KsT[c4 + 0][r] = kv.x;
                KsT[c4 + 1][r] = kv.y;
                KsT[c4 + 2][r] = kv.z;
                KsT[c4 + 3][r] = kv.w;
                *(float4*)&Vs[r][c4] = vv;
            }
        }
        __syncthreads();

        float s[4][4] = {};
#pragma unroll
        for (int d = 0; d < 64; d++) {
            float4 a = *(const float4*)&QsT[d][ty * 4];
            float4 bq = *(const float4*)&KsT[d][tx * 4];
            float av[4] = {a.x, a.y, a.z, a.w};
            float bv[4] = {bq.x, bq.y, bq.z, bq.w};
#pragma unroll
            for (int i = 0; i < 4; i++)
#pragma unroll
                for (int j = 0; j < 4; j++)
                    s[i][j] = fmaf(av[i], bv[j], s[i][j]);
        }
        // mask out-of-range keys (cross-attn tail)
        if (kt * 64 + 64 > Sk) {
#pragma unroll
            for (int j = 0; j < 4; j++)
                if (kt * 64 + tx * 4 + j >= Sk)
#pragma unroll
                    for (int i = 0; i < 4; i++) s[i][j] = -1e30f;
        }
#pragma unroll
        for (int i = 0; i < 4; i++) {
            float mx = fmaxf(fmaxf(s[i][0], s[i][1]), fmaxf(s[i][2], s[i][3]));
#pragma unroll
            for (int off = 1; off < 16; off <<= 1)
                mx = fmaxf(mx, __shfl_xor_sync(0xffffffffu, mx, off));
            float mnew = fmaxf(m_i[i], mx);
            float corr = __expf(m_i[i] - mnew);
            m_i[i] = mnew;
            float rs = 0.f;
#pragma unroll
            for (int j = 0; j < 4; j++) {
                s[i][j] = __expf(s[i][j] - mnew);
                rs += s[i][j];
            }
#pragma unroll
            for (int off = 1; off < 16; off <<= 1)
                rs += __shfl_xor_sync(0xffffffffu, rs, off);
            l_i[i] = l_i[i] * corr + rs;
#pragma unroll
            for (int j = 0; j < 4; j++) o[i][j] *= corr;
            *(float4*)&Ps[ty * 4 + i][tx * 4] = make_float4(s[i][0], s[i][1], s[i][2], s[i][3]);
        }
        __syncthreads();
#pragma unroll
        for (int kj = 0; kj < 64; kj += 4) {
            float4 p[4];
#pragma unroll
            for (int i = 0; i < 4; i++) p[i] = *(const float4*)&Ps[ty * 4 + i][kj];
#pragma unroll
            for (int jj = 0; jj < 4; jj++) {
                float4 vr = *(const float4*)&Vs[kj + jj][tx * 4];
#pragma unroll
                for (int i = 0; i < 4; i++) {
                    float pv = (jj == 0) ? p[i].x : (jj == 1) ? p[i].y : (jj == 2) ? p[i].z : p[i].w;
                    o[i][0] = fmaf(pv, vr.x, o[i][0]);
                    o[i][1] = fmaf(pv, vr.y, o[i][1]);
                    o[i][2] = fmaf(pv, vr.z, o[i][2]);
                    o[i][3] = fmaf(pv, vr.w, o[i][3]);
                }
            }
        }
    }
#pragma unroll
    for (int i = 0; i < 4; i++) {
        float inv = 1.f / l_i[i];
        float4 r = make_float4(o[i][0] * inv, o[i][1] * inv, o[i][2] * inv, o[i][3] * inv);
        *(float4*)&O[qbase + (size_t)(q0 + ty * 4 + i) * ld + tx * 4] = r;
    }
}

// ---------------------------------------------------------------------------
// GEGLU activation: act[r,c] = u * gelu_exact(g), u=proj[r,c], g=proj[r,c+2048]
// ---------------------------------------------------------------------------
__global__ __launch_bounds__(256) void geglu_kernel(
    const float* __restrict__ proj, float* __restrict__ act)
{
    int idx = blockIdx.x * 256 + threadIdx.x;   // one float4 each
    int r = idx >> 9;                           // 512 float4 per row
    int c4 = (idx & 511) * 4;
    float4 u = *(const float4*)&proj[(size_t)r * FF2 + c4];
    float4 g = *(const float4*)&proj[(size_t)r * FF2 + FF_INNER + c4];
    float4 o;
    o.x = u.x * 0.5f * g.x * (1.f + erff(g.x * 0.70710678118654752f));
    o.y = u.y * 0.5f * g.y * (1.f + erff(g.y * 0.70710678118654752f));
    o.z = u.z * 0.5f * g.z * (1.f + erff(g.z * 0.70710678118654752f));
    o.w = u.w * 0.5f * g.w * (1.f + erff(g.w * 0.70710678118654752f));
    *(float4*)&act[(size_t)r * FF_INNER + c4] = o;
}

// ---------------------------------------------------------------------------
extern "C" void kernel_launch(void* const* d_in, const int* in_sizes, int n_in,
                              void* d_out, int out_size)
{
    const float* x     = (const float*)d_in[0];
    const float* enc   = (const float*)d_in[1];
    const float* ln1_g = (const float*)d_in[2];
    const float* ln1_b = (const float*)d_in[3];
    const float* wq1   = (const float*)d_in[4];
    const float* wk1   = (const float*)d_in[5];
    const float* wv1   = (const float*)d_in[6];
    const float* wo1   = (const float*)d_in[7];
    const float* bo1   = (const float*)d_in[8];
    const float* ln2_g = (const float*)d_in[9];
    const float* ln2_b = (const float*)d_in[10];
    const float* wq2   = (const float*)d_in[11];
    const float* wk2   = (const float*)d_in[12];
    const float* wv2   = (const float*)d_in[13];
    const float* wo2   = (const float*)d_in[14];
    const float* bo2   = (const float*)d_in[15];
    const float* ln3_g = (const float*)d_in[16];
    const float* ln3_b = (const float*)d_in[17];
    const float* wg    = (const float*)d_in[18];
    const float* bg    = (const float*)d_in[19];
    const float* wf    = (const float*)d_in[20];
    const float* bf    = (const float*)d_in[21];
    float* out = (float*)d_out;

    float *h, *q, *k, *v, *a, *x1, *x2, *proj, *act;
    cudaGetSymbolAddress((void**)&h,    g_h);
    cudaGetSymbolAddress((void**)&q,    g_q);
    cudaGetSymbolAddress((void**)&k,    g_k);
    cudaGetSymbolAddress((void**)&v,    g_v);
    cudaGetSymbolAddress((void**)&a,    g_a);
    cudaGetSymbolAddress((void**)&x1,   g_x1);
    cudaGetSymbolAddress((void**)&x2,   g_x2);
    cudaGetSymbolAddress((void**)&proj, g_proj);
    cudaGetSymbolAddress((void**)&act,  g_act);

    dim3 blk(256);
    dim3 g44(4, 64);   // N=512, M=8192
    dim3 gc(4, 5);     // N=512, M=616
    dim3 gff(32, 64);  // N=4096, M=8192

    // ---- self-attention block ----
    ln_kernel<<<1024, blk>>>(x, ln1_g, ln1_b, h, ROWS);
    sgemm<false, false><<<g44, blk>>>(h, wq1, nullptr, nullptr, q, ROWS, DIM, DIM);
    sgemm<false, false><<<g44, blk>>>(h, wk1, nullptr, nullptr, k, ROWS, DIM, DIM);
    sgemm<false, false><<<g44, blk>>>(h, wv1, nullptr, nullptr, v, ROWS, DIM, DIM);
    fattn<<<dim3(16, 8, 8), blk>>>(q, k, v, a, 1024, 1024);
    sgemm<true, true><<<g44, blk>>>(a, wo1, bo1, x, x1, ROWS, DIM, DIM);

    // ---- cross-attention block ----
    ln_kernel<<<1024, blk>>>(x1, ln2_g, ln2_b, h, ROWS);
    sgemm<false, false><<<g44, blk>>>(h, wq2, nullptr, nullptr, q, ROWS, DIM, DIM);
    sgemm<false, false><<<gc, blk>>>(enc, wk2, nullptr, nullptr, k, CROSS_ROWS, DIM, CROSS_DIM);
    sgemm<false, false><<<gc, blk>>>(enc, wv2, nullptr, nullptr, v, CROSS_ROWS, DIM, CROSS_DIM);
    fattn<<<dim3(16, 8, 8), blk>>>(q, k, v, a, 77, 77);
    sgemm<true, true><<<g44, blk>>>(a, wo2, bo2, x1, x2, ROWS, DIM, DIM);

    // ---- GEGLU feed-forward ----
    ln_kernel<<<1024, blk>>>(x2, ln3_g, ln3_b, h, ROWS);
    sgemm<true, false><<<gff, blk>>>(h, wg, bg, nullptr, proj, ROWS, FF2, DIM);
    geglu_kernel<<<(ROWS * FF_INNER / 4) / 256, blk>>>(proj, act);
    sgemm<true, true><<<g44, blk>>>(act, wf, bf, x2, out, ROWS, DIM, FF_INNER);
}

// round 2
// speedup vs baseline: 2.4672x; 2.4672x over previous
#include <cuda_runtime.h>
#include <cuda_bf16.h>
#include <math.h>

// ---------------------------------------------------------------------------
// BasicTransformerBlock on GB300 — tf32 mma.sync version.
// x:[8,1024,512], enc:[8,77,768]. Heads=8, dim_head=64.
// ---------------------------------------------------------------------------

#define DIM 512
#define ROWS 8192
#define CROSS_ROWS 616
#define CROSS_DIM 768
#define FF_INNER 2048
#define FF2 4096

__device__ float g_h[ROWS * DIM];
__device__ float g_q[ROWS * DIM];
__device__ float g_k[ROWS * DIM];
__device__ float g_v[ROWS * DIM];
__device__ float g_a[ROWS * DIM];
__device__ float g_x1[ROWS * DIM];
__device__ float g_x2[ROWS * DIM];
__device__ float g_proj[ROWS * FF2];
__device__ float g_act[ROWS * FF_INNER];

__device__ __forceinline__ unsigned f2tf(float f) {
    unsigned u; asm("cvt.rna.tf32.f32 %0, %1;" : "=r"(u) : "f"(f)); return u;
}

__device__ __forceinline__ void mma8(float* acc, const unsigned* a, const unsigned* b) {
    asm volatile(
        "mma.sync.aligned.m16n8k8.row.col.f32.tf32.tf32.f32 "
        "{%0,%1,%2,%3}, {%4,%5,%6,%7}, {%8,%9}, {%0,%1,%2,%3};"
        : "+f"(acc[0]), "+f"(acc[1]), "+f"(acc[2]), "+f"(acc[3])
        : "r"(a[0]), "r"(a[1]), "r"(a[2]), "r"(a[3]), "r"(b[0]), "r"(b[1]));
}

// ---------------------------------------------------------------------------
// LayerNorm: one warp per row of 512
// ---------------------------------------------------------------------------
__global__ __launch_bounds__(256) void ln_kernel(
    const float* __restrict__ x, const float* __restrict__ g,
    const float* __restrict__ b, float* __restrict__ out, int rows)
{
    int row = blockIdx.x * 8 + (threadIdx.x >> 5);
    int lane = threadIdx.x & 31;
    if (row >= rows) return;
    const float4* xr = (const float4*)(x + (size_t)row * DIM);
    float4 v[4];
    float sum = 0.f, sq = 0.f;
#pragma unroll
    for (int i = 0; i < 4; i++) {
        v[i] = xr[lane + i * 32];
        sum += v[i].x + v[i].y + v[i].z + v[i].w;
        sq  += v[i].x*v[i].x + v[i].y*v[i].y + v[i].z*v[i].z + v[i].w*v[i].w;
    }
#pragma unroll
    for (int off = 16; off; off >>= 1) {
        sum += __shfl_xor_sync(0xffffffffu, sum, off);
        sq  += __shfl_xor_sync(0xffffffffu, sq,  off);
    }
    float mean = sum * (1.f / DIM);
    float var  = sq * (1.f / DIM) - mean * mean;
    float rstd = rsqrtf(var + 1e-5f);
    float4* outr = (float4*)(out + (size_t)row * DIM);
#pragma unroll
    for (int i = 0; i < 4; i++) {
        int c = (lane + i * 32) * 4;
        float4 gg = *(const float4*)&g[c];
        float4 bb = *(const float4*)&b[c];
        float4 o;
        o.x = (v[i].x - mean) * rstd * gg.x + bb.x;
        o.y = (v[i].y - mean) * rstd * gg.y + bb.y;
        o.z = (v[i].z - mean) * rstd * gg.z + bb.z;
        o.w = (v[i].w - mean) * rstd * gg.w + bb.w;
        outr[lane + i * 32] = o;
    }
}

// ---------------------------------------------------------------------------
// tf32 tensor-core GEMM: C[M,N] = A[M,K] @ B[K,N] (+bias) (+res)
// 128x128x16 tile, 256 threads (8 warps, 2x4), warp tile 64x32.
// smem stride 136 => fragment LDS bank = 8*k'+m' (conflict-free).
// N%128==0, K%16==0 required; M guarded.
// ---------------------------------------------------------------------------
#define LDT 136

template <bool BIAS, bool RES>
__global__ __launch_bounds__(256) void tgemm(
    const float* __restrict__ A, const float* __restrict__ B,
    const float* __restrict__ bias, const float* __restrict__ res,
    float* __restrict__ C, int M, int N, int K)
{
    __shared__ unsigned As[2][16 * LDT];
    __shared__ unsigned Bs[2][16 * LDT];
    int tid = threadIdx.x;
    int lane = tid & 31, warp = tid >> 5;
    int wm = warp >> 2, wn = warp & 3;
    int m0 = blockIdx.y * 128, n0 = blockIdx.x * 128;

    int ar = tid >> 1;          // A row 0..127
    int ac = (tid & 1) * 8;     // A k-col base
    int bkr = tid >> 4;         // B k-row 0..15
    int bc  = (tid & 15) * 4;   // B n-col base (+64 for 2nd)

    float4 ra0, ra1, rb0, rb1;
    {
        int m = m0 + ar;
        if (m < M) {
            const float* Ap = A + (size_t)m * K + ac;
            ra0 = *(const float4*)Ap;
            ra1 = *(const float4*)(Ap + 4);
        } else {
            ra0 = make_float4(0.f,0.f,0.f,0.f); ra1 = ra0;
        }
        const float* Bp = B + (size_t)bkr * N + n0 + bc;
        rb0 = *(const float4*)Bp;
        rb1 = *(const float4*)(Bp + 64);
    }
    {
        unsigned* as = As[0];
        as[(ac+0)*LDT + ar] = f2tf(ra0.x);
        as[(ac+1)*LDT + ar] = f2tf(ra0.y);
        as[(ac+2)*LDT + ar] = f2tf(ra0.z);
        as[(ac+3)*LDT + ar] = f2tf(ra0.w);
        as[(ac+4)*LDT + ar] = f2tf(ra1.x);
        as[(ac+5)*LDT + ar] = f2tf(ra1.y);
        as[(ac+6)*LDT + ar] = f2tf(ra1.z);
        as[(ac+7)*LDT + ar] = f2tf(ra1.w);
        unsigned* bs = Bs[0];
        uint4 u0 = make_uint4(f2tf(rb0.x), f2tf(rb0.y), f2tf(rb0.z), f2tf(rb0.w));
        uint4 u1 = make_uint4(f2tf(rb1.x), f2tf(rb1.y), f2tf(rb1.z), f2tf(rb1.w));
        *(uint4*)&bs[bkr*LDT + bc] = u0;
        *(uint4*)&bs[bkr*LDT + bc + 64] = u1;
    }
    __syncthreads();

    float acc[4][4][4] = {};
    int nk = K >> 4;
    for (int kt = 0; kt < nk; kt++) {
        int cur = kt & 1;
        if (kt + 1 < nk) {
            int kg = (kt + 1) * 16;
            int m = m0 + ar;
            if (m < M) {
                const float* Ap = A + (size_t)m * K + kg + ac;
                ra0 = *(const float4*)Ap;
                ra1 = *(const float4*)(Ap + 4);
            } else {
                ra0 = make_float4(0.f,0.f,0.f,0.f); ra1 = ra0;
            }
            const float* Bp = B + (size_t)(kg + bkr) * N + n0 + bc;
            rb0 = *(const float4*)Bp;
            rb1 = *(const float4*)(Bp + 64);
        }
        const unsigned* as = As[cur];
        const unsigned* bs = Bs[cur];
#pragma unroll
        for (int ks = 0; ks < 2; ks++) {
            int kb = ks * 8;
            unsigned af[4][4], bf[4][2];
#pragma unroll
            for (int i = 0; i < 4; i++) {
                int mrow = wm * 64 + i * 16 + (lane >> 2);
                int kcol = kb + (lane & 3);
                af[i][0] = as[kcol * LDT + mrow];
                af[i][1] = as[kcol * LDT + mrow + 8];
                af[i][2] = as[(kcol + 4) * LDT + mrow];
                af[i][3] = as[(kcol + 4) * LDT + mrow + 8];
            }
#pragma unroll
            for (int j = 0; j < 4; j++) {
                int ncol = wn * 32 + j * 8 + (lane >> 2);
                int krow = kb + (lane & 3);
                bf[j][0] = bs[krow * LDT + ncol];
                bf[j][1] = bs[(krow + 4) * LDT + ncol];
            }
#pragma unroll
            for (int i = 0; i < 4; i++)
#pragma unroll
                for (int j = 0; j < 4; j++)
                    mma8(acc[i][j], af[i], bf[j]);
        }
        if (kt + 1 < nk) {
            int nxt = (kt + 1) & 1;
            unsigned* as2 = As[nxt];
            as2[(ac+0)*LDT + ar] = f2tf(ra0.x);
            as2[(ac+1)*LDT + ar] = f2tf(ra0.y);
            as2[(ac+2)*LDT + ar] = f2tf(ra0.z);
            as2[(ac+3)*LDT + ar] = f2tf(ra0.w);
            as2[(ac+4)*LDT + ar] = f2tf(ra1.x);
            as2[(ac+5)*LDT + ar] = f2tf(ra1.y);
            as2[(ac+6)*LDT + ar] = f2tf(ra1.z);
            as2[(ac+7)*LDT + ar] = f2tf(ra1.w);
            unsigned* bs2 = Bs[nxt];
            uint4 u0 = make_uint4(f2tf(rb0.x), f2tf(rb0.y), f2tf(rb0.z), f2tf(rb0.w));
            uint4 u1 = make_uint4(f2tf(rb1.x), f2tf(rb1.y), f2tf(rb1.z), f2tf(rb1.w));
            *(uint4*)&bs2[bkr*LDT + bc] = u0;
            *(uint4*)&bs2[bkr*LDT + bc + 64] = u1;
        }
        __syncthreads();
    }

#pragma unroll
    for (int i = 0; i < 4; i++) {
        int mbase = m0 + wm * 64 + i * 16 + (lane >> 2);
#pragma unroll
        for (int j = 0; j < 4; j++) {
            int n = n0 + wn * 32 + j * 8 + (lane & 3) * 2;
            float2 bb = make_float2(0.f, 0.f);
            if (BIAS) bb = *(const float2*)&bias[n];
            int m1 = mbase, m2 = mbase + 8;
            if (m1 < M) {
                float2 v = make_float2(acc[i][j][0] + bb.x, acc[i][j][1] + bb.y);
                if (RES) {
                    float2 rr = *(const float2*)&res[(size_t)m1 * N + n];
                    v.x += rr.x; v.y += rr.y;
                }
                *(float2*)&C[(size_t)m1 * N + n] = v;
            }
            if (m2 < M) {
                float2 v = make_float2(acc[i][j][2] + bb.x, acc[i][j][3] + bb.y);
                if (RES) {
                    float2 rr = *(const float2*)&res[(size_t)m2 * N + n];
                    v.x += rr.x; v.y += rr.y;
                }
                *(float2*)&C[(size_t)m2 * N + n] = v;
            }
        }
    }
}

// ---------------------------------------------------------------------------
// Flash attention with tf32 mma. 128 threads (4 warps), 64 q-rows per block.
// ---------------------------------------------------------------------------
#define LDK 68
#define LDV 72

__global__ __launch_bounds__(128) void fattn_mma(
    const float* __restrict__ Q, const float* __restrict__ K,
    const float* __restrict__ V, float* __restrict__ O,
    int kRowsPerB, int Sk)
{
    __shared__ unsigned Ks[64 * LDK];
    __shared__ unsigned Vs[64 * LDV];

    int tid = threadIdx.x;
    int lane = tid & 31, warp = tid >> 5;
    int b = blockIdx.z, h = blockIdx.y;
    int q0 = blockIdx.x * 64;
    size_t qbase = ((size_t)b * 1024 + q0) * DIM + h * 64;
    size_t kbase = (size_t)b * kRowsPerB * DIM + h * 64;

    // stage Q (scaled, tf32) via Ks, then into register A-fragments
#pragma unroll
    for (int it = 0; it < 8; it++) {
        int idx = tid + it * 128;
        int r = idx >> 4, c4 = (idx & 15) * 4;
        float4 qv = *(const float4*)&Q[qbase + (size_t)r * DIM + c4];
        uint4 u = make_uint4(f2tf(qv.x * 0.125f), f2tf(qv.y * 0.125f),
                             f2tf(qv.z * 0.125f), f2tf(qv.w * 0.125f));
        *(uint4*)&Ks[r * LDK + c4] = u;
    }
    __syncthreads();
    unsigned qa[8][4];
    {
        int r0 = warp * 16 + (lane >> 2);
#pragma unroll
        for (int kk = 0; kk < 8; kk++) {
            int c = kk * 8 + (lane & 3);
            qa[kk][0] = Ks[r0 * LDK + c];
            qa[kk][1] = Ks[(r0 + 8) * LDK + c];
            qa[kk][2] = Ks[r0 * LDK + c + 4];
            qa[kk][3] = Ks[(r0 + 8) * LDK + c + 4];
        }
    }
    __syncthreads();

    float m_[2] = {-1e30f, -1e30f};
    float l_[2] = {0.f, 0.f};
    float o[8][4] = {};

    int nkt = (Sk + 63) / 64;
    for (int kt = 0; kt < nkt; kt++) {
#pragma unroll
        for (int it = 0; it < 8; it++) {
            int idx = tid + it * 128;
            int r = idx >> 4, c4 = (idx & 15) * 4;
            int gr = kt * 64 + r;
            float4 kv, vv;
            if (gr < Sk) {
                kv = *(const float4*)&K[kbase + (size_t)gr * DIM + c4];
                vv = *(const float4*)&V[kbase + (size_t)gr * DIM + c4];
            } else {
                kv = make_float4(0.f,0.f,0.f,0.f); vv = kv;
            }
            uint4 ku = make_uint4(f2tf(kv.x), f2tf(kv.y), f2tf(kv.z), f2tf(kv.w));
            uint4 vu = make_uint4(f2tf(vv.x), f2tf(vv.y), f2tf(vv.z), f2tf(vv.w));
            *(uint4*)&Ks[r * LDK + c4] = ku;
            *(uint4*)&Vs[r * LDV + c4] = vu;
        }
        __syncthreads();

        float s[8][4] = {};
#pragma unroll
        for (int kk = 0; kk < 8; kk++) {
#pragma unroll
            for (int j = 0; j < 8; j++) {
                unsigned bk[2];
                int key = j * 8 + (lane >> 2);
                int d = kk * 8 + (lane & 3);
                bk[0] = Ks[key * LDK + d];
                bk[1] = Ks[key * LDK + d + 4];
                mma8(s[j], qa[kk], bk);
            }
        }
        if (kt * 64 + 64 > Sk) {
#pragma unroll
            for (int j = 0; j < 8; j++) {
                int cb = kt * 64 + j * 8 + (lane & 3) * 2;
                if (cb >= Sk)     { s[j][0] = -1e30f; s[j][2] = -1e30f; }
                if (cb + 1 >= Sk) { s[j][1] = -1e30f; s[j][3] = -1e30f; }
            }
        }
        float mx0 = -1e30f, mx1 = -1e30f;
#pragma unroll
        for (int j = 0; j < 8; j++) {
            mx0 = fmaxf(mx0, fmaxf(s[j][0], s[j][1]));
            mx1 = fmaxf(mx1, fmaxf(s[j][2], s[j][3]));
        }
#pragma unroll
        for (int off = 1; off < 4; off <<= 1) {
            mx0 = fmaxf(mx0, __shfl_xor_sync(0xffffffffu, mx0, off));
            mx1 = fmaxf(mx1, __shfl_xor_sync(0xffffffffu, mx1, off));
        }
        float mn0 = fmaxf(m_[0], mx0), mn1 = fmaxf(m_[1], mx1);
        float c0 = __expf(m_[0] - mn0), c1 = __expf(m_[1] - mn1);
        m_[0] = mn0; m_[1] = mn1;
        float sum0 = 0.f, sum1 = 0.f;
#pragma unroll
        for (int j = 0; j < 8; j++) {
            s[j][0] = __expf(s[j][0] - mn0); sum0 += s[j][0];
            s[j][1] = __expf(s[j][1] - mn0); sum0 += s[j][1];
            s[j][2] = __expf(s[j][2] - mn1); sum1 += s[j][2];
            s[j][3] = __expf(s[j][3] - mn1); sum1 += s[j][3];
        }
#pragma unroll
        for (int off = 1; off < 4; off <<= 1) {
            sum0 += __shfl_xor_sync(0xffffffffu, sum0, off);
            sum1 += __shfl_xor_sync(0xffffffffu, sum1, off);
        }
        l_[0] = l_[0] * c0 + sum0;
        l_[1] = l_[1] * c1 + sum1;
#pragma unroll
        for (int j = 0; j < 8; j++) {
            o[j][0] *= c0; o[j][1] *= c0;
            o[j][2] *= c1; o[j][3] *= c1;
        }

        int qq = lane & 3;
        int sl0 = (lane & ~3) | (qq >> 1);
        int sl1 = sl0 + 2;
        bool oddq = (qq & 1);
#pragma unroll
        for (int kk = 0; kk < 8; kk++) {
            float v00 = __shfl_sync(0xffffffffu, s[kk][0], sl0);
            float v01 = __shfl_sync(0xffffffffu, s[kk][1], sl0);
            float v10 = __shfl_sync(0xffffffffu, s[kk][2], sl0);
            float v11 = __shfl_sync(0xffffffffu, s[kk][3], sl0);
            float w00 = __shfl_sync(0xffffffffu, s[kk][0], sl1);
            float w01 = __shfl_sync(0xffffffffu, s[kk][1], sl1);
            float w10 = __shfl_sync(0xffffffffu, s[kk][2], sl1);
            float w11 = __shfl_sync(0xffffffffu, s[kk][3], sl1);
            unsigned pa[4];
            pa[0] = f2tf(oddq ? v01 : v00);
            pa[1] = f2tf(oddq ? v11 : v10);
            pa[2] = f2tf(oddq ? w01 : w00);
            pa[3] = f2tf(oddq ? w11 : w10);
#pragma unroll
            for (int j = 0; j < 8; j++) {
                unsigned bv[2];
                int krow = kk * 8 + (lane & 3);
                int d = j * 8 + (lane >> 2);
                bv[0] = Vs[krow * LDV + d];
                bv[1] = Vs[(krow + 4) * LDV + d];
                mma8(o[j], pa, bv);
            }
        }
        __syncthreads();
    }

    float inv0 = 1.f / l_[0], inv1 = 1.f / l_[1];
    int r0 = warp * 16 + (lane >> 2);
#pragma unroll
    for (int j = 0; j < 8; j++) {
        int col = j * 8 + (lane & 3) * 2;
        *(float2*)&O[qbase + (size_t)r0 * DIM + col] =
            make_float2(o[j][0] * inv0, o[j][1] * inv0);
        *(float2*)&O[qbase + (size_t)(r0 + 8) * DIM + col] =
            make_float2(o[j][2] * inv1, o[j][3] * inv1);
    }
}

// ---------------------------------------------------------------------------
// GEGLU activation
// ---------------------------------------------------------------------------
__global__ __launch_bounds__(256) void geglu_kernel(
    const float* __restrict__ proj, float* __restrict__ act)
{
    int idx = blockIdx.x * 256 + threadIdx.x;
    int r = idx >> 9;
    int c4 = (idx & 511) * 4;
    float4 u = *(const float4*)&proj[(size_t)r * FF2 + c4];
    float4 g = *(const float4*)&proj[(size_t)r * FF2 + FF_INNER + c4];
    float4 o;
    o.x = u.x * 0.5f * g.x * (1.f + erff(g.x * 0.70710678118654752f));
    o.y = u.y * 0.5f * g.y * (1.f + erff(g.y * 0.70710678118654752f));
    o.z = u.z * 0.5f * g.z * (1.f + erff(g.z * 0.70710678118654752f));
    o.w = u.w * 0.5f * g.w * (1.f + erff(g.w * 0.70710678118654752f));
    *(float4*)&act[(size_t)r * FF_INNER + c4] = o;
}

// ---------------------------------------------------------------------------
extern "C" void kernel_launch(void* const* d_in, const int* in_sizes, int n_in,
                              void* d_out, int out_size)
{
    const float* x     = (const float*)d_in[0];
    const float* enc   = (const float*)d_in[1];
    const float* ln1_g = (const float*)d_in[2];
    const float* ln1_b = (const float*)d_in[3];
    const float* wq1   = (const float*)d_in[4];
    const float* wk1   = (const float*)d_in[5];
    const float* wv1   = (const float*)d_in[6];
    const float* wo1   = (const float*)d_in[7];
    const float* bo1   = (const float*)d_in[8];
    const float* ln2_g = (const float*)d_in[9];
    const float* ln2_b = (const float*)d_in[10];
    const float* wq2   = (const float*)d_in[11];
    const float* wk2   = (const float*)d_in[12];
    const float* wv2   = (const float*)d_in[13];
    const float* wo2   = (const float*)d_in[14];
    const float* bo2   = (const float*)d_in[15];
    const float* ln3_g = (const float*)d_in[16];
    const float* ln3_b = (const float*)d_in[17];
    const float* wg    = (const float*)d_in[18];
    const float* bg    = (const float*)d_in[19];
    const float* wf    = (const float*)d_in[20];
    const float* bf    = (const float*)d_in[21];
    float* out = (float*)d_out;

    float *h, *q, *k, *v, *a, *x1, *x2, *proj, *act;
    cudaGetSymbolAddress((void**)&h,    g_h);
    cudaGetSymbolAddress((void**)&q,    g_q);
    cudaGetSymbolAddress((void**)&k,    g_k);
    cudaGetSymbolAddress((void**)&v,    g_v);
    cudaGetSymbolAddress((void**)&a,    g_a);
    cudaGetSymbolAddress((void**)&x1,   g_x1);
    cudaGetSymbolAddress((void**)&x2,   g_x2);
    cudaGetSymbolAddress((void**)&proj, g_proj);
    cudaGetSymbolAddress((void**)&act,  g_act);

    dim3 blk(256);
    dim3 g44(4, 64);   // N=512, M=8192
    dim3 gc(4, 5);     // N=512, M=616
    dim3 gff(32, 64);  // N=4096, M=8192

    // ---- self-attention block ----
    ln_kernel<<<1024, blk>>>(x, ln1_g, ln1_b, h, ROWS);
    tgemm<false, false><<<g44, blk>>>(h, wq1, nullptr, nullptr, q, ROWS, DIM, DIM);
    tgemm<false, false><<<g44, blk>>>(h, wk1, nullptr, nullptr, k, ROWS, DIM, DIM);
    tgemm<false, false><<<g44, blk>>>(h, wv1, nullptr, nullptr, v, ROWS, DIM, DIM);
    fattn_mma<<<dim3(16, 8, 8), 128>>>(q, k, v, a, 1024, 1024);
    tgemm<true, true><<<g44, blk>>>(a, wo1, bo1, x, x1, ROWS, DIM, DIM);

    // ---- cross-attention block ----
    ln_kernel<<<1024, blk>>>(x1, ln2_g, ln2_b, h, ROWS);
    tgemm<false, false><<<g44, blk>>>(h, wq2, nullptr, nullptr, q, ROWS, DIM, DIM);
    tgemm<false, false><<<gc, blk>>>(enc, wk2, nullptr, nullptr, k, CROSS_ROWS, DIM, CROSS_DIM);
    tgemm<false, false><<<gc, blk>>>(enc, wv2, nullptr, nullptr, v, CROSS_ROWS, DIM, CROSS_DIM);
    fattn_mma<<<dim3(16, 8, 8), 128>>>(q, k, v, a, 77, 77);
    tgemm<true, true><<<g44, blk>>>(a, wo2, bo2, x1, x2, ROWS, DIM, DIM);

    // ---- GEGLU feed-forward ----
    ln_kernel<<<1024, blk>>>(x2, ln3_g, ln3_b, h, ROWS);
    tgemm<true, false><<<gff, blk>>>(h, wg, bg, nullptr, proj, ROWS, FF2, DIM);
    geglu_kernel<<<(ROWS * FF_INNER / 4) / 256, blk>>>(proj, act);
    tgemm<true, true><<<g44, blk>>>(act, wf, bf, x2, out, ROWS, DIM, FF_INNER);
}

// round 3
// speedup vs baseline: 2.6608x; 1.0785x over previous
#include <cuda_runtime.h>
#include <cuda_bf16.h>
#include <math.h>

// ---------------------------------------------------------------------------
// BasicTransformerBlock on GB300 — tf32 mma.sync, cp.async + ldmatrix version.
// Raw fp32 fed to HMMA.tf32 (hardware truncates to tf32 => no CVT needed).
// x:[8,1024,512], enc:[8,77,768]. Heads=8, dim_head=64.
// ---------------------------------------------------------------------------

#define DIM 512
#define ROWS 8192
#define CROSS_ROWS 616
#define CROSS_DIM 768
#define FF_INNER 2048
#define FF2 4096

__device__ float g_h[ROWS * DIM];
__device__ float g_q[ROWS * DIM];
__device__ float g_k[ROWS * DIM];
__device__ float g_v[ROWS * DIM];
__device__ float g_a[ROWS * DIM];
__device__ float g_x1[ROWS * DIM];
__device__ float g_x2[ROWS * DIM];
__device__ float g_proj[ROWS * FF2];
__device__ float g_act[ROWS * FF_INNER];

__device__ __forceinline__ void mma8(float* acc, const unsigned* a, const unsigned* b) {
    asm volatile(
        "mma.sync.aligned.m16n8k8.row.col.f32.tf32.tf32.f32 "
        "{%0,%1,%2,%3}, {%4,%5,%6,%7}, {%8,%9}, {%0,%1,%2,%3};"
        : "+f"(acc[0]), "+f"(acc[1]), "+f"(acc[2]), "+f"(acc[3])
        : "r"(a[0]), "r"(a[1]), "r"(a[2]), "r"(a[3]), "r"(b[0]), "r"(b[1]));
}

__device__ __forceinline__ void ldsm4(unsigned& r0, unsigned& r1, unsigned& r2, unsigned& r3,
                                      unsigned addr) {
    asm volatile("ldmatrix.sync.aligned.m8n8.x4.shared.b16 {%0,%1,%2,%3}, [%4];"
                 : "=r"(r0), "=r"(r1), "=r"(r2), "=r"(r3) : "r"(addr));
}

__device__ __forceinline__ void cpa16(unsigned dst, const void* src, bool pred) {
    int sz = pred ? 16 : 0;
    asm volatile("cp.async.cg.shared.global [%0], [%1], 16, %2;"
                 :: "r"(dst), "l"(src), "r"(sz) : "memory");
}
__device__ __forceinline__ void cpa_commit() {
    asm volatile("cp.async.commit_group;" ::: "memory");
}
__device__ __forceinline__ void cpa_wait0() {
    asm volatile("cp.async.wait_group 0;" ::: "memory");
}

// ---------------------------------------------------------------------------
// LayerNorm: one warp per row of 512
// ---------------------------------------------------------------------------
__global__ __launch_bounds__(256) void ln_kernel(
    const float* __restrict__ x, const float* __restrict__ g,
    const float* __restrict__ b, float* __restrict__ out, int rows)
{
    int row = blockIdx.x * 8 + (threadIdx.x >> 5);
    int lane = threadIdx.x & 31;
    if (row >= rows) return;
    const float4* xr = (const float4*)(x + (size_t)row * DIM);
    float4 v[4];
    float sum = 0.f, sq = 0.f;
#pragma unroll
    for (int i = 0; i < 4; i++) {
        v[i] = xr[lane + i * 32];
        sum += v[i].x + v[i].y + v[i].z + v[i].w;
        sq  += v[i].x*v[i].x + v[i].y*v[i].y + v[i].z*v[i].z + v[i].w*v[i].w;
    }
#pragma unroll
    for (int off = 16; off; off >>= 1) {
        sum += __shfl_xor_sync(0xffffffffu, sum, off);
        sq  += __shfl_xor_sync(0xffffffffu, sq,  off);
    }
    float mean = sum * (1.f / DIM);
    float var  = sq * (1.f / DIM) - mean * mean;
    float rstd = rsqrtf(var + 1e-5f);
    float4* outr = (float4*)(out + (size_t)row * DIM);
#pragma unroll
    for (int i = 0; i < 4; i++) {
        int c = (lane + i * 32) * 4;
        float4 gg = *(const float4*)&g[c];
        float4 bb = *(const float4*)&b[c];
        float4 o;
        o.x = (v[i].x - mean) * rstd * gg.x + bb.x;
        o.y = (v[i].y - mean) * rstd * gg.y + bb.y;
        o.z = (v[i].z - mean) * rstd * gg.z + bb.z;
        o.w = (v[i].w - mean) * rstd * gg.w + bb.w;
        outr[lane + i * 32] = o;
    }
}

// ---------------------------------------------------------------------------
// tf32 tensor-core GEMM with cp.async double buffering + ldmatrix A frags.
// C[M,N] = A[M,K]@B[K,N] (+bias)(+res). 128x128x16 tile, 256 thr, warp 64x32.
// As: [m][k] 16 floats/row, XOR-swizzled 16B chunks within 128B lines.
//     addr(m,k) = (m>>1)*128 + (((m&1)<<2 | k>>2) ^ ((m>>1)&7))*16 + (k&3)*4
// Bs: [k][n] stride 136 floats (conflict-free scalar frag loads).
// ---------------------------------------------------------------------------
#define LDB 136
#define A_STG 8192               // bytes per A stage (128*16*4)
#define B_STG (16 * LDB * 4)     // bytes per B stage

template <bool BIAS, bool RES>
__global__ __launch_bounds__(256) void tgemm(
    const float* __restrict__ A, const float* __restrict__ B,
    const float* __restrict__ bias, const float* __restrict__ res,
    float* __restrict__ C, int M, int N, int K)
{
    __shared__ float As[2][128 * 16];
    __shared__ float Bs[2][16 * LDB];

    int tid = threadIdx.x;
    int lane = tid & 31, warp = tid >> 5;
    int wm = warp >> 2, wn = warp & 3;
    int m0 = blockIdx.y * 128, n0 = blockIdx.x * 128;

    unsigned sA = (unsigned)__cvta_generic_to_shared(As);
    unsigned sB = (unsigned)__cvta_generic_to_shared(Bs);

    // ---- A staging map: thread -> row ar, chunks {ach, ach+1} (k = ach*4..) ----
    int ar = tid >> 1;
    int ach = (tid & 1) * 2;
    int aline = ar >> 1;
    unsigned aoff0 = aline * 128 + (((((ar & 1) << 2) | ach)     ) ^ (aline & 7)) * 16;
    unsigned aoff1 = aline * 128 + (((((ar & 1) << 2) | (ach + 1))) ^ (aline & 7)) * 16;
    bool aval = (m0 + ar) < M;
    const float* agp = A + (size_t)(aval ? (m0 + ar) : 0) * K + ach * 4;

    // ---- B staging map: thread -> k-row bkr, n cols bn..bn+7 ----
    int bkr = tid >> 4;
    int bn = (tid & 15) * 8;
    const float* bgp = B + (size_t)bkr * N + n0 + bn;
    unsigned boff0 = (bkr * LDB + bn) * 4;
    unsigned boff1 = (bkr * LDB + bn + 4) * 4;

    // ---- A fragment ldmatrix lane addressing ----
    int frow = (lane & 7) | (((lane >> 3) & 1) << 3);  // 0..15
    int fc = lane >> 4;                                 // 0..1
    int l7 = (frow >> 1) & 7;
    unsigned fpos0 = ((((frow & 1) << 2) | fc)       ^ l7) * 16;
    unsigned fpos1 = ((((frow & 1) << 2) | (2 + fc)) ^ l7) * 16;
    unsigned fbase = (wm * 32 + (frow >> 1)) * 128;

    float acc[4][4][4] = {};
    int nk = K >> 4;

    // prologue: stage 0 <- ktile 0
    cpa16(sA + aoff0, agp, aval);
    cpa16(sA + aoff1, agp + 4, aval);
    cpa16(sB + boff0, bgp, true);
    cpa16(sB + boff1, bgp + 4, true);
    cpa_commit();

    for (int kt = 0; kt < nk; kt++) {
        int cur = kt & 1;
        cpa_wait0();
        __syncthreads();
        if (kt + 1 < nk) {
            int nxt = (kt + 1) & 1;
            const float* ag = agp + (kt + 1) * 16;
            const float* bg = bgp + (size_t)(kt + 1) * 16 * N;
            cpa16(sA + nxt * A_STG + aoff0, ag, aval);
            cpa16(sA + nxt * A_STG + aoff1, ag + 4, aval);
            cpa16(sB + nxt * B_STG + boff0, bg, true);
            cpa16(sB + nxt * B_STG + boff1, bg + 4, true);
            cpa_commit();
        }
        const float* bs = Bs[cur];
        unsigned abase = sA + cur * A_STG + fbase;
#pragma unroll
        for (int ks = 0; ks < 2; ks++) {
            unsigned bf[4][2];
            int k0 = ks * 8 + (lane & 3);
            int nc = wn * 32 + (lane >> 2);
#pragma unroll
            for (int j = 0; j < 4; j++) {
                bf[j][0] = __float_as_uint(bs[k0 * LDB + nc + j * 8]);
                bf[j][1] = __float_as_uint(bs[(k0 + 4) * LDB + nc + j * 8]);
            }
            unsigned fp = ks ? fpos1 : fpos0;
#pragma unroll
            for (int i = 0; i < 4; i++) {
                unsigned af[4];
                ldsm4(af[0], af[1], af[2], af[3], abase + i * 1024 + fp);
#pragma unroll
                for (int j = 0; j < 4; j++)
                    mma8(acc[i][j], af, bf[j]);
            }
        }
        __syncthreads();
    }

    // epilogue
#pragma unroll
    for (int i = 0; i < 4; i++) {
        int mbase = m0 + wm * 64 + i * 16 + (lane >> 2);
#pragma unroll
        for (int j = 0; j < 4; j++) {
            int n = n0 + wn * 32 + j * 8 + (lane & 3) * 2;
            float2 bb = make_float2(0.f, 0.f);
            if (BIAS) bb = *(const float2*)&bias[n];
            int m1 = mbase, m2 = mbase + 8;
            if (m1 < M) {
                float2 v = make_float2(acc[i][j][0] + bb.x, acc[i][j][1] + bb.y);
                if (RES) {
                    float2 rr = *(const float2*)&res[(size_t)m1 * N + n];
                    v.x += rr.x; v.y += rr.y;
                }
                *(float2*)&C[(size_t)m1 * N + n] = v;
            }
            if (m2 < M) {
                float2 v = make_float2(acc[i][j][2] + bb.x, acc[i][j][3] + bb.y);
                if (RES) {
                    float2 rr = *(const float2*)&res[(size_t)m2 * N + n];
                    v.x += rr.x; v.y += rr.y;
                }
                *(float2*)&C[(size_t)m2 * N + n] = v;
            }
        }
    }
}

// ---------------------------------------------------------------------------
// Flash attention with tf32 mma (raw fp32 operands). 128 thr, 64 q-rows/block.
// ---------------------------------------------------------------------------
#define LDKA 68
#define LDVA 72

__global__ __launch_bounds__(128) void fattn_mma(
    const float* __restrict__ Q, const float* __restrict__ K,
    const float* __restrict__ V, float* __restrict__ O,
    int kRowsPerB, int Sk)
{
    __shared__ unsigned Ks[64 * LDKA];
    __shared__ unsigned Vs[64 * LDVA];

    int tid = threadIdx.x;
    int lane = tid & 31, warp = tid >> 5;
    int b = blockIdx.z, h = blockIdx.y;
    int q0 = blockIdx.x * 64;
    size_t qbase = ((size_t)b * 1024 + q0) * DIM + h * 64;
    size_t kbase = (size_t)b * kRowsPerB * DIM + h * 64;

    // stage Q (scaled) via Ks, then into register A-fragments
#pragma unroll
    for (int it = 0; it < 8; it++) {
        int idx = tid + it * 128;
        int r = idx >> 4, c4 = (idx & 15) * 4;
        float4 qv = *(const float4*)&Q[qbase + (size_t)r * DIM + c4];
        uint4 u = make_uint4(__float_as_uint(qv.x * 0.125f), __float_as_uint(qv.y * 0.125f),
                             __float_as_uint(qv.z * 0.125f), __float_as_uint(qv.w * 0.125f));
        *(uint4*)&Ks[r * LDKA + c4] = u;
    }
    __syncthreads();
    unsigned qa[8][4];
    {
        int r0 = warp * 16 + (lane >> 2);
#pragma unroll
        for (int kk = 0; kk < 8; kk++) {
            int c = kk * 8 + (lane & 3);
            qa[kk][0] = Ks[r0 * LDKA + c];
            qa[kk][1] = Ks[(r0 + 8) * LDKA + c];
            qa[kk][2] = Ks[r0 * LDKA + c + 4];
            qa[kk][3] = Ks[(r0 + 8) * LDKA + c + 4];
        }
    }
    __syncthreads();

    float m_[2] = {-1e30f, -1e30f};
    float l_[2] = {0.f, 0.f};
    float o[8][4] = {};

    int nkt = (Sk + 63) / 64;
    for (int kt = 0; kt < nkt; kt++) {
#pragma unroll
        for (int it = 0; it < 8; it++) {
            int idx = tid + it * 128;
            int r = idx >> 4, c4 = (idx & 15) * 4;
            int gr = kt * 64 + r;
            float4 kv, vv;
            if (gr < Sk) {
                kv = *(const float4*)&K[kbase + (size_t)gr * DIM + c4];
                vv = *(const float4*)&V[kbase + (size_t)gr * DIM + c4];
            } else {
                kv = make_float4(0.f,0.f,0.f,0.f); vv = kv;
            }
            uint4 ku = make_uint4(__float_as_uint(kv.x), __float_as_uint(kv.y),
                                  __float_as_uint(kv.z), __float_as_uint(kv.w));
            uint4 vu = make_uint4(__float_as_uint(vv.x), __float_as_uint(vv.y),
                                  __float_as_uint(vv.z), __float_as_uint(vv.w));
            *(uint4*)&Ks[r * LDKA + c4] = ku;
            *(uint4*)&Vs[r * LDVA + c4] = vu;
        }
        __syncthreads();

        float s[8][4] = {};
#pragma unroll
        for (int kk = 0; kk < 8; kk++) {
#pragma unroll
            for (int j = 0; j < 8; j++) {
                unsigned bk[2];
                int key = j * 8 + (lane >> 2);
                int d = kk * 8 + (lane & 3);
                bk[0] = Ks[key * LDKA + d];
                bk[1] = Ks[key * LDKA + d + 4];
                mma8(s[j], qa[kk], bk);
            }
        }
        if (kt * 64 + 64 > Sk) {
#pragma unroll
            for (int j = 0; j < 8; j++) {
                int cb = kt * 64 + j * 8 + (lane & 3) * 2;
                if (cb >= Sk)     { s[j][0] = -1e30f; s[j][2] = -1e30f; }
                if (cb + 1 >= Sk) { s[j][1] = -1e30f; s[j][3] = -1e30f; }
            }
        }
        float mx0 = -1e30f, mx1 = -1e30f;
#pragma unroll
        for (int j = 0; j < 8; j++) {
            mx0 = fmaxf(mx0, fmaxf(s[j][0], s[j][1]));
            mx1 = fmaxf(mx1, fmaxf(s[j][2], s[j][3]));
        }
#pragma unroll
        for (int off = 1; off < 4; off <<= 1) {
            mx0 = fmaxf(mx0, __shfl_xor_sync(0xffffffffu, mx0, off));
            mx1 = fmaxf(mx1, __shfl_xor_sync(0xffffffffu, mx1, off));
        }
        float mn0 = fmaxf(m_[0], mx0), mn1 = fmaxf(m_[1], mx1);
        float c0 = __expf(m_[0] - mn0), c1 = __expf(m_[1] - mn1);
        m_[0] = mn0; m_[1] = mn1;
        float sum0 = 0.f, sum1 = 0.f;
#pragma unroll
        for (int j = 0; j < 8; j++) {
            s[j][0] = __expf(s[j][0] - mn0); sum0 += s[j][0];
            s[j][1] = __expf(s[j][1] - mn0); sum0 += s[j][1];
            s[j][2] = __expf(s[j][2] - mn1); sum1 += s[j][2];
            s[j][3] = __expf(s[j][3] - mn1); sum1 += s[j][3];
        }
#pragma unroll
        for (int off = 1; off < 4; off <<= 1) {
            sum0 += __shfl_xor_sync(0xffffffffu, sum0, off);
            sum1 += __shfl_xor_sync(0xffffffffu, sum1, off);
        }
        l_[0] = l_[0] * c0 + sum0;
        l_[1] = l_[1] * c1 + sum1;
#pragma unroll
        for (int j = 0; j < 8; j++) {
            o[j][0] *= c0; o[j][1] *= c0;
            o[j][2] *= c1; o[j][3] *= c1;
        }

        int qq = lane & 3;
        int sl0 = (lane & ~3) | (qq >> 1);
        int sl1 = sl0 + 2;
        bool oddq = (qq & 1);
#pragma unroll
        for (int kk = 0; kk < 8; kk++) {
            float v00 = __shfl_sync(0xffffffffu, s[kk][0], sl0);
            float v01 = __shfl_sync(0xffffffffu, s[kk][1], sl0);
            float v10 = __shfl_sync(0xffffffffu, s[kk][2], sl0);
            float v11 = __shfl_sync(0xffffffffu, s[kk][3], sl0);
            float w00 = __shfl_sync(0xffffffffu, s[kk][0], sl1);
            float w01 = __shfl_sync(0xffffffffu, s[kk][1], sl1);
            float w10 = __shfl_sync(0xffffffffu, s[kk][2], sl1);
            float w11 = __shfl_sync(0xffffffffu, s[kk][3], sl1);
            unsigned pa[4];
            pa[0] = __float_as_uint(oddq ? v01 : v00);
            pa[1] = __float_as_uint(oddq ? v11 : v10);
            pa[2] = __float_as_uint(oddq ? w01 : w00);
            pa[3] = __float_as_uint(oddq ? w11 : w10);
#pragma unroll
            for (int j = 0; j < 8; j++) {
                unsigned bv[2];
                int krow = kk * 8 + (lane & 3);
                int d = j * 8 + (lane >> 2);
                bv[0] = Vs[krow * LDVA + d];
                bv[1] = Vs[(krow + 4) * LDVA + d];
                mma8(o[j], pa, bv);
            }
        }
        __syncthreads();
    }

    float inv0 = 1.f / l_[0], inv1 = 1.f / l_[1];
    int r0 = warp * 16 + (lane >> 2);
#pragma unroll
    for (int j = 0; j < 8; j++) {
        int col = j * 8 + (lane & 3) * 2;
        *(float2*)&O[qbase + (size_t)r0 * DIM + col] =
            make_float2(o[j][0] * inv0, o[j][1] * inv0);
        *(float2*)&O[qbase + (size_t)(r0 + 8) * DIM + col] =
            make_float2(o[j][2] * inv1, o[j][3] * inv1);
    }
}

// ---------------------------------------------------------------------------
// GEGLU activation
// ---------------------------------------------------------------------------
__global__ __launch_bounds__(256) void geglu_kernel(
    const float* __restrict__ proj, float* __restrict__ act)
{
    int idx = blockIdx.x * 256 + threadIdx.x;
    int r = idx >> 9;
    int c4 = (idx & 511) * 4;
    float4 u = *(const float4*)&proj[(size_t)r * FF2 + c4];
    float4 g = *(const float4*)&proj[(size_t)r * FF2 + FF_INNER + c4];
    float4 o;
    o.x = u.x * 0.5f * g.x * (1.f + erff(g.x * 0.70710678118654752f));
    o.y = u.y * 0.5f * g.y * (1.f + erff(g.y * 0.70710678118654752f));
    o.z = u.z * 0.5f * g.z * (1.f + erff(g.z * 0.70710678118654752f));
    o.w = u.w * 0.5f * g.w * (1.f + erff(g.w * 0.70710678118654752f));
    *(float4*)&act[(size_t)r * FF_INNER + c4] = o;
}

// ---------------------------------------------------------------------------
extern "C" void kernel_launch(void* const* d_in, const int* in_sizes, int n_in,
                              void* d_out, int out_size)
{
    const float* x     = (const float*)d_in[0];
    const float* enc   = (const float*)d_in[1];
    const float* ln1_g = (const float*)d_in[2];
    const float* ln1_b = (const float*)d_in[3];
    const float* wq1   = (const float*)d_in[4];
    const float* wk1   = (const float*)d_in[5];
    const float* wv1   = (const float*)d_in[6];
    const float* wo1   = (const float*)d_in[7];
    const float* bo1   = (const float*)d_in[8];
    const float* ln2_g = (const float*)d_in[9];
    const float* ln2_b = (const float*)d_in[10];
    const float* wq2   = (const float*)d_in[11];
    const float* wk2   = (const float*)d_in[12];
    const float* wv2   = (const float*)d_in[13];
    const float* wo2   = (const float*)d_in[14];
    const float* bo2   = (const float*)d_in[15];
    const float* ln3_g = (const float*)d_in[16];
    const float* ln3_b = (const float*)d_in[17];
    const float* wg    = (const float*)d_in[18];
    const float* bg    = (const float*)d_in[19];
    const float* wf    = (const float*)d_in[20];
    const float* bf    = (const float*)d_in[21];
    float* out = (float*)d_out;

    float *h, *q, *k, *v, *a, *x1, *x2, *proj, *act;
    cudaGetSymbolAddress((void**)&h,    g_h);
    cudaGetSymbolAddress((void**)&q,    g_q);
    cudaGetSymbolAddress((void**)&k,    g_k);
    cudaGetSymbolAddress((void**)&v,    g_v);
    cudaGetSymbolAddress((void**)&a,    g_a);
    cudaGetSymbolAddress((void**)&x1,   g_x1);
    cudaGetSymbolAddress((void**)&x2,   g_x2);
    cudaGetSymbolAddress((void**)&proj, g_proj);
    cudaGetSymbolAddress((void**)&act,  g_act);

    dim3 blk(256);
    dim3 g44(4, 64);   // N=512, M=8192
    dim3 gc(4, 5);     // N=512, M=616
    dim3 gff(32, 64);  // N=4096, M=8192

    // ---- self-attention block ----
    ln_kernel<<<1024, blk>>>(x, ln1_g, ln1_b, h, ROWS);
    tgemm<false, false><<<g44, blk>>>(h, wq1, nullptr, nullptr, q, ROWS, DIM, DIM);
    tgemm<false, false><<<g44, blk>>>(h, wk1, nullptr, nullptr, k, ROWS, DIM, DIM);
    tgemm<false, false><<<g44, blk>>>(h, wv1, nullptr, nullptr, v, ROWS, DIM, DIM);
    fattn_mma<<<dim3(16, 8, 8), 128>>>(q, k, v, a, 1024, 1024);
    tgemm<true, true><<<g44, blk>>>(a, wo1, bo1, x, x1, ROWS, DIM, DIM);

    // ---- cross-attention block ----
    ln_kernel<<<1024, blk>>>(x1, ln2_g, ln2_b, h, ROWS);
    tgemm<false, false><<<g44, blk>>>(h, wq2, nullptr, nullptr, q, ROWS, DIM, DIM);
    tgemm<false, false><<<gc, blk>>>(enc, wk2, nullptr, nullptr, k, CROSS_ROWS, DIM, CROSS_DIM);
    tgemm<false, false><<<gc, blk>>>(enc, wv2, nullptr, nullptr, v, CROSS_ROWS, DIM, CROSS_DIM);
    fattn_mma<<<dim3(16, 8, 8), 128>>>(q, k, v, a, 77, 77);
    tgemm<true, true><<<g44, blk>>>(a, wo2, bo2, x1, x2, ROWS, DIM, DIM);

    // ---- GEGLU feed-forward ----
    ln_kernel<<<1024, blk>>>(x2, ln3_g, ln3_b, h, ROWS);
    tgemm<true, false><<<gff, blk>>>(h, wg, bg, nullptr, proj, ROWS, FF2, DIM);
    geglu_kernel<<<(ROWS * FF_INNER / 4) / 256, blk>>>(proj, act);
    tgemm<true, true><<<g44, blk>>>(act, wf, bf, x2, out, ROWS, DIM, FF_INNER);
}

// round 4
// speedup vs baseline: 2.8136x; 1.0574x over previous
#include <cuda_runtime.h>
#include <cuda_bf16.h>
#include <math.h>

// ---------------------------------------------------------------------------
// BasicTransformerBlock on GB300 — tf32 mma.sync, 4-stage cp.async GEMM +
// double-buffered flash attention. Raw fp32 fed to HMMA.tf32.
// ---------------------------------------------------------------------------

#define DIM 512
#define ROWS 8192
#define CROSS_ROWS 616
#define CROSS_DIM 768
#define FF_INNER 2048
#define FF2 4096

__device__ float g_h[ROWS * DIM];
__device__ float g_q[ROWS * DIM];
__device__ float g_k[ROWS * DIM];
__device__ float g_v[ROWS * DIM];
__device__ float g_a[ROWS * DIM];
__device__ float g_x1[ROWS * DIM];
__device__ float g_x2[ROWS * DIM];
__device__ float g_proj[ROWS * FF2];
__device__ float g_act[ROWS * FF_INNER];

__device__ __forceinline__ void mma8(float* acc, const unsigned* a, const unsigned* b) {
    asm volatile(
        "mma.sync.aligned.m16n8k8.row.col.f32.tf32.tf32.f32 "
        "{%0,%1,%2,%3}, {%4,%5,%6,%7}, {%8,%9}, {%0,%1,%2,%3};"
        : "+f"(acc[0]), "+f"(acc[1]), "+f"(acc[2]), "+f"(acc[3])
        : "r"(a[0]), "r"(a[1]), "r"(a[2]), "r"(a[3]), "r"(b[0]), "r"(b[1]));
}

__device__ __forceinline__ void ldsm4(unsigned& r0, unsigned& r1, unsigned& r2, unsigned& r3,
                                      unsigned addr) {
    asm volatile("ldmatrix.sync.aligned.m8n8.x4.shared.b16 {%0,%1,%2,%3}, [%4];"
                 : "=r"(r0), "=r"(r1), "=r"(r2), "=r"(r3) : "r"(addr));
}

__device__ __forceinline__ void cpa16(unsigned dst, const void* src, bool pred) {
    int sz = pred ? 16 : 0;
    asm volatile("cp.async.cg.shared.global [%0], [%1], 16, %2;"
                 :: "r"(dst), "l"(src), "r"(sz) : "memory");
}
__device__ __forceinline__ void cpa_commit() {
    asm volatile("cp.async.commit_group;" ::: "memory");
}
template <int N>
__device__ __forceinline__ void cpa_wait() {
    asm volatile("cp.async.wait_group %0;" :: "n"(N) : "memory");
}

// ---------------------------------------------------------------------------
// LayerNorm: one warp per row of 512
// ---------------------------------------------------------------------------
__global__ __launch_bounds__(256) void ln_kernel(
    const float* __restrict__ x, const float* __restrict__ g,
    const float* __restrict__ b, float* __restrict__ out, int rows)
{
    int row = blockIdx.x * 8 + (threadIdx.x >> 5);
    int lane = threadIdx.x & 31;
    if (row >= rows) return;
    const float4* xr = (const float4*)(x + (size_t)row * DIM);
    float4 v[4];
    float sum = 0.f, sq = 0.f;
#pragma unroll
    for (int i = 0; i < 4; i++) {
        v[i] = xr[lane + i * 32];
        sum += v[i].x + v[i].y + v[i].z + v[i].w;
        sq  += v[i].x*v[i].x + v[i].y*v[i].y + v[i].z*v[i].z + v[i].w*v[i].w;
    }
#pragma unroll
    for (int off = 16; off; off >>= 1) {
        sum += __shfl_xor_sync(0xffffffffu, sum, off);
        sq  += __shfl_xor_sync(0xffffffffu, sq,  off);
    }
    float mean = sum * (1.f / DIM);
    float var  = sq * (1.f / DIM) - mean * mean;
    float rstd = rsqrtf(var + 1e-5f);
    float4* outr = (float4*)(out + (size_t)row * DIM);
#pragma unroll
    for (int i = 0; i < 4; i++) {
        int c = (lane + i * 32) * 4;
        float4 gg = *(const float4*)&g[c];
        float4 bb = *(const float4*)&b[c];
        float4 o;
        o.x = (v[i].x - mean) * rstd * gg.x + bb.x;
        o.y = (v[i].y - mean) * rstd * gg.y + bb.y;
        o.z = (v[i].z - mean) * rstd * gg.z + bb.z;
        o.w = (v[i].w - mean) * rstd * gg.w + bb.w;
        outr[lane + i * 32] = o;
    }
}

// ---------------------------------------------------------------------------
// tf32 GEMM, 4-stage cp.async pipeline, one barrier per k-tile.
// C[M,N]=A[M,K]@B[K,N] (+bias)(+res). 128x128x16 tile, 256 thr, warp 64x32.
// As: [m][k] XOR-swizzled 16B chunks; Bs: [k][n] stride 136.
// ---------------------------------------------------------------------------
#define LDB 136
#define A_STG 8192
#define B_STG (16 * LDB * 4)
#define NSTG 4

template <bool BIAS, bool RES>
__global__ __launch_bounds__(256) void tgemm(
    const float* __restrict__ A, const float* __restrict__ B,
    const float* __restrict__ bias, const float* __restrict__ res,
    float* __restrict__ C, int M, int N, int K)
{
    __shared__ float As[NSTG][128 * 16];
    __shared__ float Bs[NSTG][16 * LDB];

    int tid = threadIdx.x;
    int lane = tid & 31, warp = tid >> 5;
    int wm = warp >> 2, wn = warp & 3;
    int m0 = blockIdx.y * 128, n0 = blockIdx.x * 128;

    unsigned sA = (unsigned)__cvta_generic_to_shared(As);
    unsigned sB = (unsigned)__cvta_generic_to_shared(Bs);

    // A staging: thread -> row ar, chunks {ach, ach+1}
    int ar = tid >> 1;
    int ach = (tid & 1) * 2;
    int aline = ar >> 1;
    unsigned aoff0 = aline * 128 + (((((ar & 1) << 2) | ach)      ) ^ (aline & 7)) * 16;
    unsigned aoff1 = aline * 128 + (((((ar & 1) << 2) | (ach + 1))) ^ (aline & 7)) * 16;
    bool aval = (m0 + ar) < M;
    const float* agp = A + (size_t)(aval ? (m0 + ar) : 0) * K + ach * 4;

    // B staging: thread -> k-row bkr, n cols bn..bn+7
    int bkr = tid >> 4;
    int bn = (tid & 15) * 8;
    const float* bgp = B + (size_t)bkr * N + n0 + bn;
    unsigned boff0 = (bkr * LDB + bn) * 4;
    unsigned boff1 = (bkr * LDB + bn + 4) * 4;

    // A fragment ldmatrix lane addressing
    int frow = (lane & 7) | (((lane >> 3) & 1) << 3);
    int fc = lane >> 4;
    int l7 = (frow >> 1) & 7;
    unsigned fpos0 = ((((frow & 1) << 2) | fc)       ^ l7) * 16;
    unsigned fpos1 = ((((frow & 1) << 2) | (2 + fc)) ^ l7) * 16;
    unsigned fbase = (wm * 32 + (frow >> 1)) * 128;

    float acc[4][4][4] = {};
    int nk = K >> 4;

    // prologue: stages 0..2
#pragma unroll
    for (int t = 0; t < NSTG - 1; t++) {
        if (t < nk) {
            const float* ag = agp + t * 16;
            const float* bg = bgp + (size_t)t * 16 * N;
            cpa16(sA + t * A_STG + aoff0, ag, aval);
            cpa16(sA + t * A_STG + aoff1, ag + 4, aval);
            cpa16(sB + t * B_STG + boff0, bg, true);
            cpa16(sB + t * B_STG + boff1, bg + 4, true);
        }
        cpa_commit();
    }

    for (int kt = 0; kt < nk; kt++) {
        int cur = kt & (NSTG - 1);
        cpa_wait<NSTG - 2>();
        __syncthreads();
        // prefetch kt+3 into slot (kt+3)&3 (old tile kt-1, everyone done)
        {
            int tpre = kt + NSTG - 1;
            if (tpre < nk) {
                int s = tpre & (NSTG - 1);
                const float* ag = agp + tpre * 16;
                const float* bg = bgp + (size_t)tpre * 16 * N;
                cpa16(sA + s * A_STG + aoff0, ag, aval);
                cpa16(sA + s * A_STG + aoff1, ag + 4, aval);
                cpa16(sB + s * B_STG + boff0, bg, true);
                cpa16(sB + s * B_STG + boff1, bg + 4, true);
            }
            cpa_commit();
        }
        const float* bs = Bs[cur];
        unsigned abase = sA + cur * A_STG + fbase;
#pragma unroll
        for (int ks = 0; ks < 2; ks++) {
            unsigned bf[4][2];
            int k0 = ks * 8 + (lane & 3);
            int nc = wn * 32 + (lane >> 2);
#pragma unroll
            for (int j = 0; j < 4; j++) {
                bf[j][0] = __float_as_uint(bs[k0 * LDB + nc + j * 8]);
                bf[j][1] = __float_as_uint(bs[(k0 + 4) * LDB + nc + j * 8]);
            }
            unsigned fp = ks ? fpos1 : fpos0;
#pragma unroll
            for (int i = 0; i < 4; i++) {
                unsigned af[4];
                ldsm4(af[0], af[1], af[2], af[3], abase + i * 1024 + fp);
#pragma unroll
                for (int j = 0; j < 4; j++)
                    mma8(acc[i][j], af, bf[j]);
            }
        }
    }

    __syncthreads();
#pragma unroll
    for (int i = 0; i < 4; i++) {
        int mbase = m0 + wm * 64 + i * 16 + (lane >> 2);
#pragma unroll
        for (int j = 0; j < 4; j++) {
            int n = n0 + wn * 32 + j * 8 + (lane & 3) * 2;
            float2 bb = make_float2(0.f, 0.f);
            if (BIAS) bb = *(const float2*)&bias[n];
            int m1 = mbase, m2 = mbase + 8;
            if (m1 < M) {
                float2 v = make_float2(acc[i][j][0] + bb.x, acc[i][j][1] + bb.y);
                if (RES) {
                    float2 rr = *(const float2*)&res[(size_t)m1 * N + n];
                    v.x += rr.x; v.y += rr.y;
                }
                *(float2*)&C[(size_t)m1 * N + n] = v;
            }
            if (m2 < M) {
                float2 v = make_float2(acc[i][j][2] + bb.x, acc[i][j][3] + bb.y);
                if (RES) {
                    float2 rr = *(const float2*)&res[(size_t)m2 * N + n];
                    v.x += rr.x; v.y += rr.y;
                }
                *(float2*)&C[(size_t)m2 * N + n] = v;
            }
        }
    }
}

// ---------------------------------------------------------------------------
// Flash attention, tf32 mma, cp.async double-buffered K/V tiles.
// 128 threads (4 warps), 64 q-rows/block, 64-key tiles.
// ---------------------------------------------------------------------------
#define LDKA 68
#define LDVA 72
#define K_STG (64 * LDKA * 4)
#define V_STG (64 * LDVA * 4)

__global__ __launch_bounds__(128) void fattn_mma(
    const float* __restrict__ Q, const float* __restrict__ K,
    const float* __restrict__ V, float* __restrict__ O,
    int kRowsPerB, int Sk)
{
    __shared__ unsigned Ks[2][64 * LDKA];
    __shared__ unsigned Vs[2][64 * LDVA];

    int tid = threadIdx.x;
    int lane = tid & 31, warp = tid >> 5;
    int b = blockIdx.z, h = blockIdx.y;
    int q0 = blockIdx.x * 64;
    size_t qbase = ((size_t)b * 1024 + q0) * DIM + h * 64;
    size_t kbase = (size_t)b * kRowsPerB * DIM + h * 64;

    unsigned sK = (unsigned)__cvta_generic_to_shared(Ks);
    unsigned sV = (unsigned)__cvta_generic_to_shared(Vs);

    // stage Q (scaled) via Ks[0], then into register A-fragments
#pragma unroll
    for (int it = 0; it < 8; it++) {
        int idx = tid + it * 128;
        int r = idx >> 4, c4 = (idx & 15) * 4;
        float4 qv = *(const float4*)&Q[qbase + (size_t)r * DIM + c4];
        uint4 u = make_uint4(__float_as_uint(qv.x * 0.125f), __float_as_uint(qv.y * 0.125f),
                             __float_as_uint(qv.z * 0.125f), __float_as_uint(qv.w * 0.125f));
        *(uint4*)&Ks[0][r * LDKA + c4] = u;
    }
    __syncthreads();
    unsigned qa[8][4];
    {
        int r0 = warp * 16 + (lane >> 2);
#pragma unroll
        for (int kk = 0; kk < 8; kk++) {
            int c = kk * 8 + (lane & 3);
            qa[kk][0] = Ks[0][r0 * LDKA + c];
            qa[kk][1] = Ks[0][(r0 + 8) * LDKA + c];
            qa[kk][2] = Ks[0][r0 * LDKA + c + 4];
            qa[kk][3] = Ks[0][(r0 + 8) * LDKA + c + 4];
        }
    }
    __syncthreads();

    int nkt = (Sk + 63) / 64;

    // prologue: prefetch tiles 0 and 1
#pragma unroll
    for (int t = 0; t < 2; t++) {
        if (t < nkt) {
#pragma unroll
            for (int it = 0; it < 8; it++) {
                int c = tid + it * 128;
                int r = c >> 4, c4 = (c & 15) * 4;
                int gr = t * 64 + r;
                bool ok = gr < Sk;
                const float* kp = &K[kbase + (size_t)gr * DIM + c4];
                const float* vp = &V[kbase + (size_t)gr * DIM + c4];
                cpa16(sK + t * K_STG + (r * LDKA + c4) * 4, kp, ok);
                cpa16(sV + t * V_STG + (r * LDVA + c4) * 4, vp, ok);
            }
        }
        cpa_commit();
    }

    float m_[2] = {-1e30f, -1e30f};
    float l_[2] = {0.f, 0.f};
    float o[8][4] = {};

    for (int kt = 0; kt < nkt; kt++) {
        int cur = kt & 1;
        cpa_wait<1>();
        __syncthreads();

        const unsigned* ks = Ks[cur];
        const unsigned* vs = Vs[cur];

        float s[8][4] = {};
#pragma unroll
        for (int kk = 0; kk < 8; kk++) {
#pragma unroll
            for (int j = 0; j < 8; j++) {
                unsigned bk[2];
                int key = j * 8 + (lane >> 2);
                int d = kk * 8 + (lane & 3);
                bk[0] = ks[key * LDKA + d];
                bk[1] = ks[key * LDKA + d + 4];
                mma8(s[j], qa[kk], bk);
            }
        }
        if (kt * 64 + 64 > Sk) {
#pragma unroll
            for (int j = 0; j < 8; j++) {
                int cb = kt * 64 + j * 8 + (lane & 3) * 2;
                if (cb >= Sk)     { s[j][0] = -1e30f; s[j][2] = -1e30f; }
                if (cb + 1 >= Sk) { s[j][1] = -1e30f; s[j][3] = -1e30f; }
            }
        }
        float mx0 = -1e30f, mx1 = -1e30f;
#pragma unroll
        for (int j = 0; j < 8; j++) {
            mx0 = fmaxf(mx0, fmaxf(s[j][0], s[j][1]));
            mx1 = fmaxf(mx1, fmaxf(s[j][2], s[j][3]));
        }
#pragma unroll
        for (int off = 1; off < 4; off <<= 1) {
            mx0 = fmaxf(mx0, __shfl_xor_sync(0xffffffffu, mx0, off));
            mx1 = fmaxf(mx1, __shfl_xor_sync(0xffffffffu, mx1, off));
        }
        float mn0 = fmaxf(m_[0], mx0), mn1 = fmaxf(m_[1], mx1);
        float c0 = __expf(m_[0] - mn0), c1 = __expf(m_[1] - mn1);
        m_[0] = mn0; m_[1] = mn1;
        float sum0 = 0.f, sum1 = 0.f;
#pragma unroll
        for (int j = 0; j < 8; j++) {
            s[j][0] = __expf(s[j][0] - mn0); sum0 += s[j][0];
            s[j][1] = __expf(s[j][1] - mn0); sum0 += s[j][1];
            s[j][2] = __expf(s[j][2] - mn1); sum1 += s[j][2];
            s[j][3] = __expf(s[j][3] - mn1); sum1 += s[j][3];
        }
#pragma unroll
        for (int off = 1; off < 4; off <<= 1) {
            sum0 += __shfl_xor_sync(0xffffffffu, sum0, off);
            sum1 += __shfl_xor_sync(0xffffffffu, sum1, off);
        }
        l_[0] = l_[0] * c0 + sum0;
        l_[1] = l_[1] * c1 + sum1;
#pragma unroll
        for (int j = 0; j < 8; j++) {
            o[j][0] *= c0; o[j][1] *= c0;
            o[j][2] *= c1; o[j][3] *= c1;
        }

        int qq = lane & 3;
        int sl0 = (lane & ~3) | (qq >> 1);
        int sl1 = sl0 + 2;
        bool oddq = (qq & 1);
#pragma unroll
        for (int kk = 0; kk < 8; kk++) {
            float v00 = __shfl_sync(0xffffffffu, s[kk][0], sl0);
            float v01 = __shfl_sync(0xffffffffu, s[kk][1], sl0);
            float v10 = __shfl_sync(0xffffffffu, s[kk][2], sl0);
            float v11 = __shfl_sync(0xffffffffu, s[kk][3], sl0);
            float w00 = __shfl_sync(0xffffffffu, s[kk][0], sl1);
            float w01 = __shfl_sync(0xffffffffu, s[kk][1], sl1);
            float w10 = __shfl_sync(0xffffffffu, s[kk][2], sl1);
            float w11 = __shfl_sync(0xffffffffu, s[kk][3], sl1);
            unsigned pa[4];
            pa[0] = __float_as_uint(oddq ? v01 : v00);
            pa[1] = __float_as_uint(oddq ? v11 : v10);
            pa[2] = __float_as_uint(oddq ? w01 : w00);
            pa[3] = __float_as_uint(oddq ? w11 : w10);
#pragma unroll
            for (int j = 0; j < 8; j++) {
                unsigned bv[2];
                int krow = kk * 8 + (lane & 3);
                int d = j * 8 + (lane >> 2);
                bv[0] = vs[krow * LDVA + d];
                bv[1] = vs[(krow + 4) * LDVA + d];
                mma8(o[j], pa, bv);
            }
        }
        __syncthreads();   // all warps done reading stage cur
        // prefetch tile kt+2 into stage cur
        {
            int t = kt + 2;
            if (t < nkt) {
#pragma unroll
                for (int it = 0; it < 8; it++) {
                    int c = tid + it * 128;
                    int r = c >> 4, c4 = (c & 15) * 4;
                    int gr = t * 64 + r;
                    bool ok = gr < Sk;
                    const float* kp = &K[kbase + (size_t)gr * DIM + c4];
                    const float* vp = &V[kbase + (size_t)gr * DIM + c4];
                    cpa16(sK + cur * K_STG + (r * LDKA + c4) * 4, kp, ok);
                    cpa16(sV + cur * V_STG + (r * LDVA + c4) * 4, vp, ok);
                }
            }
            cpa_commit();
        }
    }

    float inv0 = 1.f / l_[0], inv1 = 1.f / l_[1];
    int r0 = warp * 16 + (lane >> 2);
#pragma unroll
    for (int j = 0; j < 8; j++) {
        int col = j * 8 + (lane & 3) * 2;
        *(float2*)&O[qbase + (size_t)r0 * DIM + col] =
            make_float2(o[j][0] * inv0, o[j][1] * inv0);
        *(float2*)&O[qbase + (size_t)(r0 + 8) * DIM + col] =
            make_float2(o[j][2] * inv1, o[j][3] * inv1);
    }
}

// ---------------------------------------------------------------------------
// GEGLU activation
// ---------------------------------------------------------------------------
__global__ __launch_bounds__(256) void geglu_kernel(
    const float* __restrict__ proj, float* __restrict__ act)
{
    int idx = blockIdx.x * 256 + threadIdx.x;
    int r = idx >> 9;
    int c4 = (idx & 511) * 4;
    float4 u = *(const float4*)&proj[(size_t)r * FF2 + c4];
    float4 g = *(const float4*)&proj[(size_t)r * FF2 + FF_INNER + c4];
    float4 o;
    o.x = u.x * 0.5f * g.x * (1.f + erff(g.x * 0.70710678118654752f));
    o.y = u.y * 0.5f * g.y * (1.f + erff(g.y * 0.70710678118654752f));
    o.z = u.z * 0.5f * g.z * (1.f + erff(g.z * 0.70710678118654752f));
    o.w = u.w * 0.5f * g.w * (1.f + erff(g.w * 0.70710678118654752f));
    *(float4*)&act[(size_t)r * FF_INNER + c4] = o;
}

// ---------------------------------------------------------------------------
extern "C" void kernel_launch(void* const* d_in, const int* in_sizes, int n_in,
                              void* d_out, int out_size)
{
    const float* x     = (const float*)d_in[0];
    const float* enc   = (const float*)d_in[1];
    const float* ln1_g = (const float*)d_in[2];
    const float* ln1_b = (const float*)d_in[3];
    const float* wq1   = (const float*)d_in[4];
    const float* wk1   = (const float*)d_in[5];
    const float* wv1   = (const float*)d_in[6];
    const float* wo1   = (const float*)d_in[7];
    const float* bo1   = (const float*)d_in[8];
    const float* ln2_g = (const float*)d_in[9];
    const float* ln2_b = (const float*)d_in[10];
    const float* wq2   = (const float*)d_in[11];
    const float* wk2   = (const float*)d_in[12];
    const float* wv2   = (const float*)d_in[13];
    const float* wo2   = (const float*)d_in[14];
    const float* bo2   = (const float*)d_in[15];
    const float* ln3_g = (const float*)d_in[16];
    const float* ln3_b = (const float*)d_in[17];
    const float* wg    = (const float*)d_in[18];
    const float* bg    = (const float*)d_in[19];
    const float* wf    = (const float*)d_in[20];
    const float* bf    = (const float*)d_in[21];
    float* out = (float*)d_out;

    float *h, *q, *k, *v, *a, *x1, *x2, *proj, *act;
    cudaGetSymbolAddress((void**)&h,    g_h);
    cudaGetSymbolAddress((void**)&q,    g_q);
    cudaGetSymbolAddress((void**)&k,    g_k);
    cudaGetSymbolAddress((void**)&v,    g_v);
    cudaGetSymbolAddress((void**)&a,    g_a);
    cudaGetSymbolAddress((void**)&x1,   g_x1);
    cudaGetSymbolAddress((void**)&x2,   g_x2);
    cudaGetSymbolAddress((void**)&proj, g_proj);
    cudaGetSymbolAddress((void**)&act,  g_act);

    dim3 blk(256);
    dim3 g44(4, 64);   // N=512, M=8192
    dim3 gc(4, 5);     // N=512, M=616
    dim3 gff(32, 64);  // N=4096, M=8192

    // ---- self-attention block ----
    ln_kernel<<<1024, blk>>>(x, ln1_g, ln1_b, h, ROWS);
    tgemm<false, false><<<g44, blk>>>(h, wq1, nullptr, nullptr, q, ROWS, DIM, DIM);
    tgemm<false, false><<<g44, blk>>>(h, wk1, nullptr, nullptr, k, ROWS, DIM, DIM);
    tgemm<false, false><<<g44, blk>>>(h, wv1, nullptr, nullptr, v, ROWS, DIM, DIM);
    fattn_mma<<<dim3(16, 8, 8), 128>>>(q, k, v, a, 1024, 1024);
    tgemm<true, true><<<g44, blk>>>(a, wo1, bo1, x, x1, ROWS, DIM, DIM);

    // ---- cross-attention block ----
    ln_kernel<<<1024, blk>>>(x1, ln2_g, ln2_b, h, ROWS);
    tgemm<false, false><<<g44, blk>>>(h, wq2, nullptr, nullptr, q, ROWS, DIM, DIM);
    tgemm<false, false><<<gc, blk>>>(enc, wk2, nullptr, nullptr, k, CROSS_ROWS, DIM, CROSS_DIM);
    tgemm<false, false><<<gc, blk>>>(enc, wv2, nullptr, nullptr, v, CROSS_ROWS, DIM, CROSS_DIM);
    fattn_mma<<<dim3(16, 8, 8), 128>>>(q, k, v, a, 77, 77);
    tgemm<true, true><<<g44, blk>>>(a, wo2, bo2, x1, x2, ROWS, DIM, DIM);

    // ---- GEGLU feed-forward ----
    ln_kernel<<<1024, blk>>>(x2, ln3_g, ln3_b, h, ROWS);
    tgemm<true, false><<<gff, blk>>>(h, wg, bg, nullptr, proj, ROWS, FF2, DIM);
    geglu_kernel<<<(ROWS * FF_INNER / 4) / 256, blk>>>(proj, act);
    tgemm<true, true><<<g44, blk>>>(act, wf, bf, x2, out, ROWS, DIM, FF_INNER);
}

// round 7
// speedup vs baseline: 4.8034x; 1.7072x over previous
#include <cuda_runtime.h>
#include <cuda_fp16.h>
#include <math.h>

// ---------------------------------------------------------------------------
// BasicTransformerBlock on GB300 — fp16 mma.sync (m16n8k16) everywhere.
// fp32 accumulate; activations/weights converted to fp16 outside hot loops.
// x:[8,1024,512], enc:[8,77,768]. Heads=8, dim_head=64.
// ---------------------------------------------------------------------------

#define DIM 512
#define ROWS 8192
#define CROSS_ROWS 616
#define CROSS_DIM 768
#define FF_INNER 2048
#define FF2 4096

// transposed fp16 weight offsets (each [N,K] row-major)
#define OFF_WQ1 0u
#define OFF_WK1 262144u
#define OFF_WV1 524288u
#define OFF_WO1 786432u
#define OFF_WQ2 1048576u
#define OFF_WO2 1310720u
#define OFF_WK2 1572864u
#define OFF_WV2 1966080u
#define OFF_WG  2359296u
#define OFF_WF  4456448u
#define WT_TOTAL 5505024u

__device__ __half g_h[ROWS * DIM];
__device__ __half g_q[ROWS * DIM];
__device__ __half g_k[ROWS * DIM];
__device__ __half g_v[ROWS * DIM];
__device__ __half g_a[ROWS * DIM];
__device__ __half g_act[ROWS * FF_INNER];
__device__ float  g_proj[ROWS * FF2];
__device__ float  g_x1[ROWS * DIM];
__device__ float  g_x2[ROWS * DIM];
__device__ __half g_wth[WT_TOTAL];
__device__ __half g_ench[CROSS_ROWS * CROSS_DIM];

// ---------------------------------------------------------------------------
// helpers
// ---------------------------------------------------------------------------
__device__ __forceinline__ void mma16(float* acc, const unsigned* a, const unsigned* b) {
    asm volatile(
        "mma.sync.aligned.m16n8k16.row.col.f32.f16.f16.f32 "
        "{%0,%1,%2,%3}, {%4,%5,%6,%7}, {%8,%9}, {%0,%1,%2,%3};"
        : "+f"(acc[0]), "+f"(acc[1]), "+f"(acc[2]), "+f"(acc[3])
        : "r"(a[0]), "r"(a[1]), "r"(a[2]), "r"(a[3]), "r"(b[0]), "r"(b[1]));
}
__device__ __forceinline__ void ldsm4(unsigned& r0, unsigned& r1, unsigned& r2, unsigned& r3,
                                      unsigned addr) {
    asm volatile("ldmatrix.sync.aligned.m8n8.x4.shared.b16 {%0,%1,%2,%3}, [%4];"
                 : "=r"(r0), "=r"(r1), "=r"(r2), "=r"(r3) : "r"(addr));
}
__device__ __forceinline__ void ldsm4t(unsigned& r0, unsigned& r1, unsigned& r2, unsigned& r3,
                                       unsigned addr) {
    asm volatile("ldmatrix.sync.aligned.m8n8.x4.trans.shared.b16 {%0,%1,%2,%3}, [%4];"
                 : "=r"(r0), "=r"(r1), "=r"(r2), "=r"(r3) : "r"(addr));
}
__device__ __forceinline__ void cpa16(unsigned dst, const void* src, bool pred) {
    int sz = pred ? 16 : 0;
    asm volatile("cp.async.cg.shared.global [%0], [%1], 16, %2;"
                 :: "r"(dst), "l"(src), "r"(sz) : "memory");
}
__device__ __forceinline__ void cpa_commit() {
    asm volatile("cp.async.commit_group;" ::: "memory");
}
template <int N>
__device__ __forceinline__ void cpa_wait() {
    asm volatile("cp.async.wait_group %0;" :: "n"(N) : "memory");
}
__device__ __forceinline__ unsigned packh2(float lo, float hi) {
    __half2 h = __floats2half2_rn(lo, hi);
    return *reinterpret_cast<unsigned*>(&h);
}

// ---------------------------------------------------------------------------
// weight transpose+convert: src float [K,N] -> dst half [N,K]
// grid=(N/32, K/32), block=(32,8)
// ---------------------------------------------------------------------------
__global__ __launch_bounds__(256) void transp(
    const float* __restrict__ src, __half* __restrict__ dst, int K, int N)
{
    __shared__ float t[32][33];
    int tx = threadIdx.x, ty = threadIdx.y;
    int bx = blockIdx.x * 32, by = blockIdx.y * 32;
#pragma unroll
    for (int i = 0; i < 4; i++)
        t[ty + 8 * i][tx] = src[(size_t)(by + ty + 8 * i) * N + bx + tx];
    __syncthreads();
#pragma unroll
    for (int i = 0; i < 4; i++)
        dst[(size_t)(bx + ty + 8 * i) * K + by + tx] = __float2half(t[tx][ty + 8 * i]);
}

// float -> half elementwise (enc)
__global__ __launch_bounds__(256) void f2h_kernel(
    const float* __restrict__ src, __half* __restrict__ dst, int n)
{
    int i = blockIdx.x * 256 + threadIdx.x;
    if (i < n) dst[i] = __float2half(src[i]);
}

// ---------------------------------------------------------------------------
// fp16 tensor-core GEMM: C[M,N] = A[M,K] @ BT[N,K]^T  (+bias)(+res)
// A,BT half. 128x128x64 tile, 256 thr (8 warps 2x4), warp 64x32.
// 3-stage cp.async, one barrier/tile. Rows staged as 128B (64 half) with
// XOR swizzle: addr(r,c)=r*128+((c^(r&7))<<4), c=chunk 0..7.
// Requires N%128==0, K%64==0. M guarded.
// ---------------------------------------------------------------------------
#define HA_STG 16384
#define HB_OFF 49152
#define HB_STG 16384
#define GH_SMEM 98304

template <bool BIAS, bool RES, bool OUTH>
__global__ __launch_bounds__(256) void gemm_h(
    const __half* __restrict__ A, const __half* __restrict__ BT,
    const float* __restrict__ bias, const float* __restrict__ res,
    void* __restrict__ Cout, int M, int N, int K)
{
    extern __shared__ char smem[];
    unsigned sb = (unsigned)__cvta_generic_to_shared(smem);

    int tid = threadIdx.x;
    int lane = tid & 31, warp = tid >> 5;
    int wm = warp >> 2, wn = warp & 3;
    int m0 = blockIdx.y * 128, n0 = blockIdx.x * 128;

    // staging: thread -> row tid>>1, chunks (tid&1)*4..+3
    int srow = tid >> 1, sch = (tid & 1) * 4;
    bool aval = (m0 + srow) < M;
    const __half* ag = A + (size_t)(aval ? m0 + srow : 0) * K + sch * 8;
    const __half* bg = BT + (size_t)(n0 + srow) * K + sch * 8;
    unsigned ssw[4];
#pragma unroll
    for (int c = 0; c < 4; c++)
        ssw[c] = srow * 128 + (((sch + c) ^ (srow & 7)) << 4);

    auto stage = [&](int t, int buf) {
        unsigned ab = sb + buf * HA_STG;
        unsigned bb = sb + HB_OFF + buf * HB_STG;
        const __half* a = ag + t * 64;
        const __half* b = bg + t * 64;
#pragma unroll
        for (int c = 0; c < 4; c++) cpa16(ab + ssw[c], a + c * 8, aval);
#pragma unroll
        for (int c = 0; c < 4; c++) cpa16(bb + ssw[c], b + c * 8, true);
        cpa_commit();
    };

    // ldmatrix lane addressing (A frags and B frags use same pattern)
    int mat = lane >> 3, lr = lane & 7;
    int rA = wm * 64 + (mat & 1) * 8 + lr;       // + i*16
    int rB = wn * 32 + (mat & 1) * 8 + lr;       // + p*16
    int cOff = mat >> 1;                          // + ks*2

    float acc[4][4][4] = {};
    int nk = K >> 6;

    stage(0, 0);
    stage(1, 1);

    for (int t = 0; t < nk; t++) {
        int buf = t % 3;
        cpa_wait<1>();
        __syncthreads();
        if (t + 2 < nk) stage(t + 2, (t + 2) % 3);
        else cpa_commit();   // keep group count consistent
        unsigned abase = sb + buf * HA_STG;
        unsigned bbase = sb + HB_OFF + buf * HB_STG;
#pragma unroll
        for (int ks = 0; ks < 4; ks++) {
            int cc = ks * 2 + cOff;
            unsigned bf[4][2];
#pragma unroll
            for (int p = 0; p < 2; p++) {
                int r = rB + p * 16;
                unsigned q0, q1, q2, q3;
                ldsm4(q0, q1, q2, q3, bbase + r * 128 + ((cc ^ (r & 7)) << 4));
                bf[2 * p][0] = q0; bf[2 * p][1] = q2;
                bf[2 * p + 1][0] = q1; bf[2 * p + 1][1] = q3;
            }
#pragma unroll
            for (int i = 0; i < 4; i++) {
                int r = rA + i * 16;
                unsigned af[4];
                ldsm4(af[0], af[1], af[2], af[3],
                      abase + r * 128 + ((cc ^ (r & 7)) << 4));
#pragma unroll
                for (int j = 0; j < 4; j++)
                    mma16(acc[i][j], af, bf[j]);
            }
        }
    }

    __syncthreads();
#pragma unroll
    for (int i = 0; i < 4; i++) {
        int mbase = m0 + wm * 64 + i * 16 + (lane >> 2);
#pragma unroll
        for (int j = 0; j < 4; j++) {
            int n = n0 + wn * 32 + j * 8 + (lane & 3) * 2;
            float bx = 0.f, by = 0.f;
            if (BIAS) { float2 bb = *(const float2*)&bias[n]; bx = bb.x; by = bb.y; }
            int m1 = mbase, m2 = mbase + 8;
            if (m1 < M) {
                float vx = acc[i][j][0] + bx, vy = acc[i][j][1] + by;
                if (RES) {
                    float2 rr = *(const float2*)&res[(size_t)m1 * N + n];
                    vx += rr.x; vy += rr.y;
                }
                if (OUTH)
                    *(__half2*)&((__half*)Cout)[(size_t)m1 * N + n] = __floats2half2_rn(vx, vy);
                else
                    *(float2*)&((float*)Cout)[(size_t)m1 * N + n] = make_float2(vx, vy);
            }
            if (m2 < M) {
                float vx = acc[i][j][2] + bx, vy = acc[i][j][3] + by;
                if (RES) {
                    float2 rr = *(const float2*)&res[(size_t)m2 * N + n];
                    vx += rr.x; vy += rr.y;
                }
                if (OUTH)
                    *(__half2*)&((__half*)Cout)[(size_t)m2 * N + n] = __floats2half2_rn(vx, vy);
                else
                    *(float2*)&((float*)Cout)[(size_t)m2 * N + n] = make_float2(vx, vy);
            }
        }
    }
}

// ---------------------------------------------------------------------------
// LayerNorm: one warp per row of 512, half output
// ---------------------------------------------------------------------------
__global__ __launch_bounds__(256) void ln_kernel(
    const float* __restrict__ x, const float* __restrict__ g,
    const float* __restrict__ b, __half* __restrict__ out, int rows)
{
    int row = blockIdx.x * 8 + (threadIdx.x >> 5);
    int lane = threadIdx.x & 31;
    if (row >= rows) return;
    const float4* xr = (const float4*)(x + (size_t)row * DIM);
    float4 v[4];
    float sum = 0.f, sq = 0.f;
#pragma unroll
    for (int i = 0; i < 4; i++) {
        v[i] = xr[lane + i * 32];
        sum += v[i].x + v[i].y + v[i].z + v[i].w;
        sq  += v[i].x*v[i].x + v[i].y*v[i].y + v[i].z*v[i].z + v[i].w*v[i].w;
    }
#pragma unroll
    for (int off = 16; off; off >>= 1) {
        sum += __shfl_xor_sync(0xffffffffu, sum, off);
        sq  += __shfl_xor_sync(0xffffffffu, sq,  off);
    }
    float mean = sum * (1.f / DIM);
    float var  = sq * (1.f / DIM) - mean * mean;
    float rstd = rsqrtf(var + 1e-5f);
    __half2* outr = (__half2*)(out + (size_t)row * DIM);
#pragma unroll
    for (int i = 0; i < 4; i++) {
        int c = (lane + i * 32) * 4;
        float4 gg = *(const float4*)&g[c];
        float4 bb = *(const float4*)&b[c];
        float ox = (v[i].x - mean) * rstd * gg.x + bb.x;
        float oy = (v[i].y - mean) * rstd * gg.y + bb.y;
        float oz = (v[i].z - mean) * rstd * gg.z + bb.z;
        float ow = (v[i].w - mean) * rstd * gg.w + bb.w;
        outr[(lane + i * 32) * 2]     = __floats2half2_rn(ox, oy);
        outr[(lane + i * 32) * 2 + 1] = __floats2half2_rn(oz, ow);
    }
}

// ---------------------------------------------------------------------------
// Flash attention, fp16 mma. 128 thr (4 warps), 64 q-rows/block, 64-key tiles.
// Q/K/V half in gmem. Swizzled smem rows of 128B (64 half).
// P C-frag -> A-frag identity: no shuffles.
// ---------------------------------------------------------------------------
#define FK_STG 8192

__global__ __launch_bounds__(128) void fattn_h(
    const __half* __restrict__ Q, const __half* __restrict__ K,
    const __half* __restrict__ V, __half* __restrict__ O,
    int kRowsPerB, int Sk)
{
    __shared__ __half Qs[64 * 64];
    __shared__ __half Ks[2][64 * 64];
    __shared__ __half Vs[2][64 * 64];

    int tid = threadIdx.x;
    int lane = tid & 31, warp = tid >> 5;
    int b = blockIdx.z, h = blockIdx.y;
    int q0 = blockIdx.x * 64;
    size_t qbase = ((size_t)b * 1024 + q0) * DIM + h * 64;
    size_t kbase = (size_t)b * kRowsPerB * DIM + h * 64;

    unsigned sQ = (unsigned)__cvta_generic_to_shared(Qs);
    unsigned sK = (unsigned)__cvta_generic_to_shared(Ks);
    unsigned sV = (unsigned)__cvta_generic_to_shared(Vs);

    // stage Q (512 chunks of 16B)
#pragma unroll
    for (int it = 0; it < 4; it++) {
        int c = tid + it * 128;
        int r = c >> 3, ch = c & 7;
        cpa16(sQ + r * 128 + ((ch ^ (r & 7)) << 4), Q + qbase + (size_t)r * DIM + ch * 8, true);
    }
    cpa_commit();

    int nkt = (Sk + 63) / 64;
    // prefetch K/V tiles 0,1
#pragma unroll
    for (int t = 0; t < 2; t++) {
        if (t < nkt) {
#pragma unroll
            for (int it = 0; it < 4; it++) {
                int c = tid + it * 128;
                int r = c >> 3, ch = c & 7;
                int gr = t * 64 + r;
                bool ok = gr < Sk;
                unsigned sw = r * 128 + ((ch ^ (r & 7)) << 4);
                cpa16(sK + t * FK_STG + sw, K + kbase + (size_t)gr * DIM + ch * 8, ok);
                cpa16(sV + t * FK_STG + sw, V + kbase + (size_t)gr * DIM + ch * 8, ok);
            }
        }
        cpa_commit();
    }

    // Q fragments
    int mat = lane >> 3, lr = lane & 7;
    unsigned qa[4][4];
    {
        cpa_wait<2>();   // Q group done (2 K/V groups outstanding)
        __syncthreads();
        int r = warp * 16 + (mat & 1) * 8 + lr;
#pragma unroll
        for (int ks = 0; ks < 4; ks++) {
            int cc = ks * 2 + (mat >> 1);
            ldsm4(qa[ks][0], qa[ks][1], qa[ks][2], qa[ks][3],
                  sQ + r * 128 + ((cc ^ (r & 7)) << 4));
        }
    }

    float m_[2] = {-1e30f, -1e30f};
    float l_[2] = {0.f, 0.f};
    float o[8][4] = {};

    for (int kt = 0; kt < nkt; kt++) {
        int cur = kt & 1;
        cpa_wait<1>();
        __syncthreads();

        unsigned kb = sK + cur * FK_STG;
        unsigned vb = sV + cur * FK_STG;

        // S = Q @ K^T
        float s[8][4] = {};
#pragma unroll
        for (int ks = 0; ks < 4; ks++) {
            int cc = ks * 2 + (mat >> 1);
            unsigned kf[8][2];
#pragma unroll
            for (int p = 0; p < 4; p++) {
                int r = p * 16 + (mat & 1) * 8 + lr;
                unsigned r0, r1, r2, r3;
                ldsm4(r0, r1, r2, r3, kb + r * 128 + ((cc ^ (r & 7)) << 4));
                kf[2 * p][0] = r0; kf[2 * p][1] = r2;
                kf[2 * p + 1][0] = r1; kf[2 * p + 1][1] = r3;
            }
#pragma unroll
            for (int j = 0; j < 8; j++)
                mma16(s[j], qa[ks], kf[j]);
        }
        // scale + mask
#pragma unroll
        for (int j = 0; j < 8; j++) {
            s[j][0] *= 0.125f; s[j][1] *= 0.125f; s[j][2] *= 0.125f; s[j][3] *= 0.125f;
        }
        if (kt * 64 + 64 > Sk) {
#pragma unroll
            for (int j = 0; j < 8; j++) {
                int cb = kt * 64 + j * 8 + (lane & 3) * 2;
                if (cb >= Sk)     { s[j][0] = -1e30f; s[j][2] = -1e30f; }
                if (cb + 1 >= Sk) { s[j][1] = -1e30f; s[j][3] = -1e30f; }
            }
        }
        // online softmax (rows lane>>2, lane>>2+8)
        float mx0 = -1e30f, mx1 = -1e30f;
#pragma unroll
        for (int j = 0; j < 8; j++) {
            mx0 = fmaxf(mx0, fmaxf(s[j][0], s[j][1]));
            mx1 = fmaxf(mx1, fmaxf(s[j][2], s[j][3]));
        }
#pragma unroll
        for (int off = 1; off < 4; off <<= 1) {
            mx0 = fmaxf(mx0, __shfl_xor_sync(0xffffffffu, mx0, off));
            mx1 = fmaxf(mx1, __shfl_xor_sync(0xffffffffu, mx1, off));
        }
        float mn0 = fmaxf(m_[0], mx0), mn1 = fmaxf(m_[1], mx1);
        float c0 = __expf(m_[0] - mn0), c1 = __expf(m_[1] - mn1);
        m_[0] = mn0; m_[1] = mn1;
        float sum0 = 0.f, sum1 = 0.f;
#pragma unroll
        for (int j = 0; j < 8; j++) {
            s[j][0] = __expf(s[j][0] - mn0); sum0 += s[j][0];
            s[j][1] = __expf(s[j][1] - mn0); sum0 += s[j][1];
            s[j][2] = __expf(s[j][2] - mn1); sum1 += s[j][2];
            s[j][3] = __expf(s[j][3] - mn1); sum1 += s[j][3];
        }
#pragma unroll
        for (int off = 1; off < 4; off <<= 1) {
            sum0 += __shfl_xor_sync(0xffffffffu, sum0, off);
            sum1 += __shfl_xor_sync(0xffffffffu, sum1, off);
        }
        l_[0] = l_[0] * c0 + sum0;
        l_[1] = l_[1] * c1 + sum1;
#pragma unroll
        for (int j = 0; j < 8; j++) {
            o[j][0] *= c0; o[j][1] *= c0;
            o[j][2] *= c1; o[j][3] *= c1;
        }

        // O += P @ V  (P a-frags direct from s)
#pragma unroll
        for (int kk = 0; kk < 4; kk++) {
            unsigned pa[4];
            pa[0] = packh2(s[2 * kk][0],     s[2 * kk][1]);
            pa[1] = packh2(s[2 * kk][2],     s[2 * kk][3]);
            pa[2] = packh2(s[2 * kk + 1][0], s[2 * kk + 1][1]);
            pa[3] = packh2(s[2 * kk + 1][2], s[2 * kk + 1][3]);
            int r = kk * 16 + (mat & 1) * 8 + lr;
#pragma unroll
            for (int jp = 0; jp < 4; jp++) {
                int cc = jp * 2 + (mat >> 1);
                unsigned r0, r1, r2, r3;
                ldsm4t(r0, r1, r2, r3, vb + r * 128 + ((cc ^ (r & 7)) << 4));
                unsigned vf0[2] = {r0, r1};
                unsigned vf1[2] = {r2, r3};
                mma16(o[2 * jp], pa, vf0);
                mma16(o[2 * jp + 1], pa, vf1);
            }
        }
        __syncthreads();
        // prefetch tile kt+2 into stage cur
        {
            int t = kt + 2;
            if (t < nkt) {
#pragma unroll
                for (int it = 0; it < 4; it++) {
                    int c = tid + it * 128;
                    int r = c >> 3, ch = c & 7;
                    int gr = t * 64 + r;
                    bool ok = gr < Sk;
                    unsigned sw = r * 128 + ((ch ^ (r & 7)) << 4);
                    cpa16(sK + cur * FK_STG + sw, K + kbase + (size_t)gr * DIM + ch * 8, ok);
                    cpa16(sV + cur * FK_STG + sw, V + kbase + (size_t)gr * DIM + ch * 8, ok);
                }
            }
            cpa_commit();
        }
    }

    float inv0 = 1.f / l_[0], inv1 = 1.f / l_[1];
    int r0 = warp * 16 + (lane >> 2);
#pragma unroll
    for (int j = 0; j < 8; j++) {
        int col = j * 8 + (lane & 3) * 2;
        *(__half2*)&O[qbase + (size_t)r0 * DIM + col] =
            __floats2half2_rn(o[j][0] * inv0, o[j][1] * inv0);
        *(__half2*)&O[qbase + (size_t)(r0 + 8) * DIM + col] =
            __floats2half2_rn(o[j][2] * inv1, o[j][3] * inv1);
    }
}

// ---------------------------------------------------------------------------
// GEGLU activation: float proj -> half act
// ---------------------------------------------------------------------------
__global__ __launch_bounds__(256) void geglu_kernel(
    const float* __restrict__ proj, __half* __restrict__ act)
{
    int idx = blockIdx.x * 256 + threadIdx.x;
    int r = idx >> 9;
    int c4 = (idx & 511) * 4;
    float4 u = *(const float4*)&proj[(size_t)r * FF2 + c4];
    float4 g = *(const float4*)&proj[(size_t)r * FF2 + FF_INNER + c4];
    float ox = u.x * 0.5f * g.x * (1.f + erff(g.x * 0.70710678118654752f));
    float oy = u.y * 0.5f * g.y * (1.f + erff(g.y * 0.70710678118654752f));
    float oz = u.z * 0.5f * g.z * (1.f + erff(g.z * 0.70710678118654752f));
    float ow = u.w * 0.5f * g.w * (1.f + erff(g.w * 0.70710678118654752f));
    __half2* ap = (__half2*)&act[(size_t)r * FF_INNER + c4];
    ap[0] = __floats2half2_rn(ox, oy);
    ap[1] = __floats2half2_rn(oz, ow);
}

// ---------------------------------------------------------------------------
extern "C" void kernel_launch(void* const* d_in, const int* in_sizes, int n_in,
                              void* d_out, int out_size)
{
    const float* x     = (const float*)d_in[0];
    const float* enc   = (const float*)d_in[1];
    const float* ln1_g = (const float*)d_in[2];
    const float* ln1_b = (const float*)d_in[3];
    const float* wq1   = (const float*)d_in[4];
    const float* wk1   = (const float*)d_in[5];
    const float* wv1   = (const float*)d_in[6];
    const float* wo1   = (const float*)d_in[7];
    const float* bo1   = (const float*)d_in[8];
    const float* ln2_g = (const float*)d_in[9];
    const float* ln2_b = (const float*)d_in[10];
    const float* wq2   = (const float*)d_in[11];
    const float* wk2   = (const float*)d_in[12];
    const float* wv2   = (const float*)d_in[13];
    const float* wo2   = (const float*)d_in[14];
    const float* bo2   = (const float*)d_in[15];
    const float* ln3_g = (const float*)d_in[16];
    const float* ln3_b = (const float*)d_in[17];
    const float* wg    = (const float*)d_in[18];
    const float* bg    = (const float*)d_in[19];
    const float* wf    = (const float*)d_in[20];
    const float* bf    = (const float*)d_in[21];
    float* out = (float*)d_out;

    __half *h, *q, *k, *v, *a, *act, *wt, *ench;
    float *proj, *x1, *x2;
    cudaGetSymbolAddress((void**)&h,    g_h);
    cudaGetSymbolAddress((void**)&q,    g_q);
    cudaGetSymbolAddress((void**)&k,    g_k);
    cudaGetSymbolAddress((void**)&v,    g_v);
    cudaGetSymbolAddress((void**)&a,    g_a);
    cudaGetSymbolAddress((void**)&act,  g_act);
    cudaGetSymbolAddress((void**)&wt,   g_wth);
    cudaGetSymbolAddress((void**)&ench, g_ench);
    cudaGetSymbolAddress((void**)&proj, g_proj);
    cudaGetSymbolAddress((void**)&x1,   g_x1);
    cudaGetSymbolAddress((void**)&x2,   g_x2);

    cudaFuncSetAttribute(gemm_h<false, false, true>,
                         cudaFuncAttributeMaxDynamicSharedMemorySize, GH_SMEM);
    cudaFuncSetAttribute(gemm_h<true, true, false>,
                         cudaFuncAttributeMaxDynamicSharedMemorySize, GH_SMEM);
    cudaFuncSetAttribute(gemm_h<true, false, false>,
                         cudaFuncAttributeMaxDynamicSharedMemorySize, GH_SMEM);

    dim3 blk(256);
    dim3 tb32(32, 8);

    // ---- weight transpose+convert, enc convert ----
    transp<<<dim3(16, 16),  tb32>>>(wq1, wt + OFF_WQ1, 512, 512);
    transp<<<dim3(16, 16),  tb32>>>(wk1, wt + OFF_WK1, 512, 512);
    transp<<<dim3(16, 16),  tb32>>>(wv1, wt + OFF_WV1, 512, 512);
    transp<<<dim3(16, 16),  tb32>>>(wo1, wt + OFF_WO1, 512, 512);
    transp<<<dim3(16, 16),  tb32>>>(wq2, wt + OFF_WQ2, 512, 512);
    transp<<<dim3(16, 16),  tb32>>>(wo2, wt + OFF_WO2, 512, 512);
    transp<<<dim3(16, 24),  tb32>>>(wk2, wt + OFF_WK2, 768, 512);
    transp<<<dim3(16, 24),  tb32>>>(wv2, wt + OFF_WV2, 768, 512);
    transp<<<dim3(128, 16), tb32>>>(wg,  wt + OFF_WG,  512, 4096);
    transp<<<dim3(16, 64),  tb32>>>(wf,  wt + OFF_WF,  2048, 512);
    f2h_kernel<<<(CROSS_ROWS * CROSS_DIM + 255) / 256, blk>>>(enc, ench, CROSS_ROWS * CROSS_DIM);

    dim3 g4x64(4, 64);   // N=512, M=8192
    dim3 g4x5(4, 5);     // N=512, M=616
    dim3 g32x64(32, 64); // N=4096, M=8192

    // ---- self-attention block ----
    ln_kernel<<<1024, blk>>>(x, ln1_g, ln1_b, h, ROWS);
    gemm_h<false, false, true><<<g4x64, blk, GH_SMEM>>>(h, wt + OFF_WQ1, nullptr, nullptr, q, ROWS, DIM, DIM);
    gemm_h<false, false, true><<<g4x64, blk, GH_SMEM>>>(h, wt + OFF_WK1, nullptr, nullptr, k, ROWS, DIM, DIM);
    gemm_h<false, false, true><<<g4x64, blk, GH_SMEM>>>(h, wt + OFF_WV1, nullptr, nullptr, v, ROWS, DIM, DIM);
    fattn_h<<<dim3(16, 8, 8), 128>>>(q, k, v, a, 1024, 1024);
    gemm_h<true, true, false><<<g4x64, blk, GH_SMEM>>>(a, wt + OFF_WO1, bo1, x, x1, ROWS, DIM, DIM);

    // ---- cross-attention block ----
    ln_kernel<<<1024, blk>>>(x1, ln2_g, ln2_b, h, ROWS);
    gemm_h<false, false, true><<<g4x64, blk, GH_SMEM>>>(h, wt + OFF_WQ2, nullptr, nullptr, q, ROWS, DIM, DIM);
    gemm_h<false, false, true><<<g4x5, blk, GH_SMEM>>>(ench, wt + OFF_WK2, nullptr, nullptr, k, CROSS_ROWS, DIM, CROSS_DIM);
    gemm_h<false, false, true><<<g4x5, blk, GH_SMEM>>>(ench, wt + OFF_WV2, nullptr, nullptr, v, CROSS_ROWS, DIM, CROSS_DIM);
    fattn_h<<<dim3(16, 8, 8), 128>>>(q, k, v, a, 77, 77);
    gemm_h<true, true, false><<<g4x64, blk, GH_SMEM>>>(a, wt + OFF_WO2, bo2, x1, x2, ROWS, DIM, DIM);

    // ---- GEGLU feed-forward ----
    ln_kernel<<<1024, blk>>>(x2, ln3_g, ln3_b, h, ROWS);
    gemm_h<true, false, false><<<g32x64, blk, GH_SMEM>>>(h, wt + OFF_WG, bg, nullptr, proj, ROWS, FF2, DIM);
    geglu_kernel<<<(ROWS * FF_INNER / 4) / 256, blk>>>(proj, act);
    gemm_h<true, true, false><<<g4x64, blk, GH_SMEM>>>(act, wt + OFF_WF, bf, x2, out, ROWS, DIM, FF_INNER);
}